// round 9
// baseline (speedup 1.0000x reference)
#include <cuda_runtime.h>
#include <cuda_bf16.h>
#include <math.h>
#include <stdint.h>

// Problem constants
#define NTOK  4096      // B*T
#define TSEQ  2048
#define EMBED 1024
#define NH    16
#define HDIM  64

// ---------------------------------------------------------------------------
// Scratch (device globals: allocation-free per harness rules)
// ---------------------------------------------------------------------------
__device__ __nv_bfloat16 g_xhi[(size_t)NTOK * EMBED];
__device__ __nv_bfloat16 g_xlo[(size_t)NTOK * EMBED];
__device__ __nv_bfloat16 g_Qh[(size_t)NTOK * EMBED];
__device__ __nv_bfloat16 g_Ql[(size_t)NTOK * EMBED];
__device__ __nv_bfloat16 g_Kh[(size_t)NTOK * EMBED];
__device__ __nv_bfloat16 g_Kl[(size_t)NTOK * EMBED];
__device__ __nv_bfloat16 g_Vh[(size_t)NTOK * EMBED];
__device__ __nv_bfloat16 g_Vl[(size_t)NTOK * EMBED];
__device__ __nv_bfloat16 g_ahi[(size_t)NTOK * EMBED];
__device__ __nv_bfloat16 g_alo[(size_t)NTOK * EMBED];
__device__ __nv_bfloat16 g_whi[(size_t)4 * EMBED * EMBED];  // Wq^T,Wk^T,Wv^T,Wo^T
__device__ __nv_bfloat16 g_wlo[(size_t)4 * EMBED * EMBED];

// ---------------------------------------------------------------------------
// PTX helpers (compute_103-safe: ldmatrix + mma.sync only)
// ---------------------------------------------------------------------------
__device__ __forceinline__ uint32_t smem_u32(const void* p) {
    uint32_t a;
    asm("{ .reg .u64 t; cvta.to.shared.u64 t, %1; cvt.u32.u64 %0, t; }"
        : "=r"(a) : "l"(p));
    return a;
}

__device__ __forceinline__ void ldsm_x4(uint32_t addr, uint32_t& r0, uint32_t& r1,
                                        uint32_t& r2, uint32_t& r3) {
    asm volatile("ldmatrix.sync.aligned.m8n8.x4.shared.b16 {%0,%1,%2,%3}, [%4];"
                 : "=r"(r0), "=r"(r1), "=r"(r2), "=r"(r3) : "r"(addr));
}

__device__ __forceinline__ void ldsm_x4_t(uint32_t addr, uint32_t& r0, uint32_t& r1,
                                          uint32_t& r2, uint32_t& r3) {
    asm volatile("ldmatrix.sync.aligned.m8n8.x4.trans.shared.b16 {%0,%1,%2,%3}, [%4];"
                 : "=r"(r0), "=r"(r1), "=r"(r2), "=r"(r3) : "r"(addr));
}

__device__ __forceinline__ void mma16816(float* d, const uint32_t* a,
                                         const uint32_t* b) {
    asm volatile(
        "mma.sync.aligned.m16n8k16.row.col.f32.bf16.bf16.f32 "
        "{%0,%1,%2,%3}, {%4,%5,%6,%7}, {%8,%9}, {%0,%1,%2,%3};"
        : "+f"(d[0]), "+f"(d[1]), "+f"(d[2]), "+f"(d[3])
        : "r"(a[0]), "r"(a[1]), "r"(a[2]), "r"(a[3]), "r"(b[0]), "r"(b[1]));
}

// fp32 -> (bf16 hi, bf16 lo) split
__device__ __forceinline__ void split_bf16(float v, __nv_bfloat16& h, __nv_bfloat16& l) {
    h = __float2bfloat16(v);
    l = __float2bfloat16(v - __bfloat162float(h));
}

// split a pair of floats into packed hi/lo bf16x2 words
__device__ __forceinline__ void split2(float a, float b, uint32_t& hi, uint32_t& lo) {
    __nv_bfloat16 ha = __float2bfloat16(a);
    __nv_bfloat16 hb = __float2bfloat16(b);
    __nv_bfloat162 hp = __halves2bfloat162(ha, hb);
    hi = *reinterpret_cast<uint32_t*>(&hp);
    __nv_bfloat162 lp = __floats2bfloat162_rn(a - __bfloat162float(ha),
                                              b - __bfloat162float(hb));
    lo = *reinterpret_cast<uint32_t*>(&lp);
}

// Software exp2 on the FMA pipe (no MUFU). x <= 0 expected; rel err ~2e-6.
__device__ __forceinline__ float fexp2(float x) {
    x = fmaxf(x, -125.0f);
    float t = __fadd_rn(x, 12582912.0f);              // 1.5 * 2^23: round to int
    int   k = __float_as_int(t) - 0x4B400000;
    float f = __fsub_rn(x, __fsub_rn(t, 12582912.0f)); // frac in [-0.5, 0.5]
    float p = 1.3333558146e-3f;
    p = fmaf(p, f, 9.6181291077e-3f);
    p = fmaf(p, f, 5.5504108664e-2f);
    p = fmaf(p, f, 2.4022650696e-1f);
    p = fmaf(p, f, 6.9314718056e-1f);
    p = fmaf(p, f, 1.0f);
    return p * __int_as_float((k + 127) << 23);
}

// ---------------------------------------------------------------------------
// Kernel 1: x -> xhi/xlo
// ---------------------------------------------------------------------------
__global__ __launch_bounds__(256)
void conv_x(const float* __restrict__ x, __nv_bfloat16* __restrict__ xhi,
            __nv_bfloat16* __restrict__ xlo)
{
    size_t i = ((size_t)blockIdx.x * 256 + threadIdx.x) * 4;
    float4 v = *(const float4*)(x + i);
    uint32_t h0, l0, h1, l1;
    split2(v.x, v.y, h0, l0);
    split2(v.z, v.w, h1, l1);
    uint2 ph, pl;
    ph.x = h0; ph.y = h1; pl.x = l0; pl.y = l1;
    *(uint2*)(xhi + i) = ph;
    *(uint2*)(xlo + i) = pl;
}

// ---------------------------------------------------------------------------
// Kernel 2: W [K,N] fp32 -> W^T [N,K] bf16 hi/lo (z selects among 4 weights)
// ---------------------------------------------------------------------------
__global__ __launch_bounds__(256)
void conv_wT(const float* __restrict__ W0, const float* __restrict__ W1,
             const float* __restrict__ W2, const float* __restrict__ W3,
             __nv_bfloat16* __restrict__ whi, __nv_bfloat16* __restrict__ wlo)
{
    __shared__ float tile[32][33];
    const float* W = W0;
    if (blockIdx.z == 1) W = W1;
    else if (blockIdx.z == 2) W = W2;
    else if (blockIdx.z == 3) W = W3;

    const int x = blockIdx.x * 32 + threadIdx.x;
    const int y = blockIdx.y * 32 + threadIdx.y;
#pragma unroll
    for (int j = 0; j < 32; j += 8)
        tile[threadIdx.y + j][threadIdx.x] = W[(size_t)(y + j) * EMBED + x];
    __syncthreads();

    const int xo = blockIdx.y * 32 + threadIdx.x;
    const int yo = blockIdx.x * 32 + threadIdx.y;
    const size_t zo = (size_t)blockIdx.z * EMBED * EMBED;
#pragma unroll
    for (int j = 0; j < 32; j += 8) {
        float v = tile[threadIdx.x][threadIdx.y + j];
        __nv_bfloat16 h, l;
        split_bf16(v, h, l);
        whi[zo + (size_t)(yo + j) * EMBED + xo] = h;
        wlo[zo + (size_t)(yo + j) * EMBED + xo] = l;
    }
}

// ---------------------------------------------------------------------------
// Kernel 3: bf16x3 GEMM on mma.sync.m16n8k16
//   SPLIT=1: writes bf16 hi/lo pair arrays (feeds attention)
//   SPLIT=0: writes fp32 (final output)
// ---------------------------------------------------------------------------
#define TSTR 40   // padded k-stride (bf16 elems)

__device__ __forceinline__ void ld_tile(__nv_bfloat16* s,
                                        const __nv_bfloat16* __restrict__ g,
                                        int tid)
{
#pragma unroll
    for (int it = 0; it < 2; it++) {
        const int c   = tid + it * 256;
        const int r   = c >> 2;
        const int col = (c & 3) << 3;
        uint4 v = *(const uint4*)(g + (size_t)r * EMBED + col);
        *(uint4*)(s + r * TSTR + col) = v;
    }
}

template<int SPLIT>
__global__ __launch_bounds__(256, 1)
void gemm_mma(const __nv_bfloat16* __restrict__ Ahi, const __nv_bfloat16* __restrict__ Alo,
              const __nv_bfloat16* __restrict__ Bh0, const __nv_bfloat16* __restrict__ Bh1,
              const __nv_bfloat16* __restrict__ Bh2,
              const __nv_bfloat16* __restrict__ Bl0, const __nv_bfloat16* __restrict__ Bl1,
              const __nv_bfloat16* __restrict__ Bl2,
              const float* __restrict__ c0, const float* __restrict__ c1,
              const float* __restrict__ c2,
              float* __restrict__ F0,
              __nv_bfloat16* __restrict__ H0, __nv_bfloat16* __restrict__ H1,
              __nv_bfloat16* __restrict__ H2,
              __nv_bfloat16* __restrict__ L0, __nv_bfloat16* __restrict__ L1,
              __nv_bfloat16* __restrict__ L2)
{
    __shared__ __align__(16) __nv_bfloat16 sAh[128 * TSTR];
    __shared__ __align__(16) __nv_bfloat16 sAl[128 * TSTR];
    __shared__ __align__(16) __nv_bfloat16 sBh[128 * TSTR];
    __shared__ __align__(16) __nv_bfloat16 sBl[128 * TSTR];

    const __nv_bfloat16* Bhi = Bh0;
    const __nv_bfloat16* Blo = Bl0;
    const float* bias = c0;
    __nv_bfloat16* Dh = H0;
    __nv_bfloat16* Dl = L0;
    if (blockIdx.z == 1)      { Bhi = Bh1; Blo = Bl1; bias = c1; Dh = H1; Dl = L1; }
    else if (blockIdx.z == 2) { Bhi = Bh2; Blo = Bl2; bias = c2; Dh = H2; Dl = L2; }

    const int tid    = threadIdx.x;
    const int lane   = tid & 31;
    const int wid    = tid >> 5;
    const int warp_m = wid >> 2;
    const int warp_n = wid & 3;
    const int bm     = blockIdx.y * 128;
    const int bn     = blockIdx.x * 128;

    const uint32_t aRow = warp_m * 64 + (lane & 15);
    const uint32_t aOff = aRow * (TSTR * 2) + ((lane >> 4) << 4);
    const uint32_t aHb  = smem_u32(sAh) + aOff;
    const uint32_t aLb  = smem_u32(sAl) + aOff;
    const uint32_t bg   = lane >> 3;
    const uint32_t bRow = warp_n * 32 + ((bg >> 1) << 3) + (lane & 7);
    const uint32_t bOff = bRow * (TSTR * 2) + ((bg & 1) << 4);
    const uint32_t bHb  = smem_u32(sBh) + bOff;
    const uint32_t bLb  = smem_u32(sBl) + bOff;

    float acc[4][4][4];
#pragma unroll
    for (int i = 0; i < 4; i++)
#pragma unroll
        for (int j = 0; j < 4; j++)
#pragma unroll
            for (int q = 0; q < 4; q++) acc[i][j][q] = 0.0f;

    const __nv_bfloat16* gAh = Ahi + (size_t)bm * EMBED;
    const __nv_bfloat16* gAl = Alo + (size_t)bm * EMBED;
    const __nv_bfloat16* gBh = Bhi + (size_t)bn * EMBED;
    const __nv_bfloat16* gBl = Blo + (size_t)bn * EMBED;

    for (int kb = 0; kb < EMBED / 32; kb++) {
        __syncthreads();
        const int kc = kb * 32;
        ld_tile(sAh, gAh + kc, tid);
        ld_tile(sAl, gAl + kc, tid);
        ld_tile(sBh, gBh + kc, tid);
        ld_tile(sBl, gBl + kc, tid);
        __syncthreads();

#pragma unroll
        for (int ks = 0; ks < 2; ks++) {
            uint32_t ah[4][4], al[4][4], bh[4][2], bl[4][2];
#pragma unroll
            for (int mi = 0; mi < 4; mi++) {
                const uint32_t d = mi * (16 * TSTR * 2) + ks * 32;
                ldsm_x4(aHb + d, ah[mi][0], ah[mi][1], ah[mi][2], ah[mi][3]);
                ldsm_x4(aLb + d, al[mi][0], al[mi][1], al[mi][2], al[mi][3]);
            }
#pragma unroll
            for (int np = 0; np < 2; np++) {
                const uint32_t d = np * (16 * TSTR * 2) + ks * 32;
                ldsm_x4(bHb + d, bh[np*2][0], bh[np*2][1], bh[np*2+1][0], bh[np*2+1][1]);
                ldsm_x4(bLb + d, bl[np*2][0], bl[np*2][1], bl[np*2+1][0], bl[np*2+1][1]);
            }
#pragma unroll
            for (int mi = 0; mi < 4; mi++)
#pragma unroll
                for (int ni = 0; ni < 4; ni++) {
                    mma16816(acc[mi][ni], ah[mi], bh[ni]);
                    mma16816(acc[mi][ni], ah[mi], bl[ni]);
                    mma16816(acc[mi][ni], al[mi], bh[ni]);
                }
        }
    }

#pragma unroll
    for (int ni = 0; ni < 4; ni++) {
        const int col = bn + warp_n * 32 + ni * 8 + ((lane & 3) << 1);
        const float2 bv = *(const float2*)(bias + col);
#pragma unroll
        for (int mi = 0; mi < 4; mi++) {
            const int row = bm + warp_m * 64 + mi * 16 + (lane >> 2);
            const float a0 = acc[mi][ni][0] + bv.x;
            const float a1 = acc[mi][ni][1] + bv.y;
            const float a2 = acc[mi][ni][2] + bv.x;
            const float a3 = acc[mi][ni][3] + bv.y;
            if (SPLIT) {
                uint32_t h01, l01, h23, l23;
                split2(a0, a1, h01, l01);
                split2(a2, a3, h23, l23);
                *(uint32_t*)(Dh + (size_t)row * EMBED + col)       = h01;
                *(uint32_t*)(Dl + (size_t)row * EMBED + col)       = l01;
                *(uint32_t*)(Dh + (size_t)(row + 8) * EMBED + col) = h23;
                *(uint32_t*)(Dl + (size_t)(row + 8) * EMBED + col) = l23;
            } else {
                float2 o0, o1;
                o0.x = a0; o0.y = a1; o1.x = a2; o1.y = a3;
                *(float2*)(F0 + (size_t)row * EMBED + col)       = o0;
                *(float2*)(F0 + (size_t)(row + 8) * EMBED + col) = o1;
            }
        }
    }
}

// ---------------------------------------------------------------------------
// Kernel 4: tensor-core flash attention (causal).
//   Inputs: Q/K/V as bf16 hi/lo split [B*T, 1024], head h = cols h*64..h*64+63.
//   One CTA = 64 q-rows x (head, batch). 4 warps; warp owns 16 q-rows.
//   QK^T: bf16x3 mma (Q frags cached in regs). Softmax: FFMA-pipe exp2.
//   P.V: bf16x3 mma, V consumed via ldmatrix.trans (no transpose in smem).
// ---------------------------------------------------------------------------
#define FSTR 72   // padded row stride (bf16): 144 B -> conflict-free ldmatrix

__global__ __launch_bounds__(128, 3)
void flash_attn(const __nv_bfloat16* __restrict__ Qh, const __nv_bfloat16* __restrict__ Ql,
                const __nv_bfloat16* __restrict__ Kh, const __nv_bfloat16* __restrict__ Kl,
                const __nv_bfloat16* __restrict__ Vh, const __nv_bfloat16* __restrict__ Vl,
                __nv_bfloat16* __restrict__ Oh, __nv_bfloat16* __restrict__ Ol)
{
    extern __shared__ __align__(16) __nv_bfloat16 sm[];
    __nv_bfloat16* sKh = sm;
    __nv_bfloat16* sKl = sKh + 64 * FSTR;
    __nv_bfloat16* sVh = sKl + 64 * FSTR;
    __nv_bfloat16* sVl = sVh + 64 * FSTR;
    __nv_bfloat16* sQh = sVl + 64 * FSTR;
    __nv_bfloat16* sQl = sQh + 64 * FSTR;

    const int tid  = threadIdx.x;
    const int lane = tid & 31;
    const int wid  = tid >> 5;
    const int qt   = gridDim.x - 1 - blockIdx.x;   // heavy tiles first
    const int h    = blockIdx.y;
    const int b    = blockIdx.z;

    const size_t base = (size_t)b * TSEQ * EMBED + (size_t)h * HDIM;
    const int q0 = qt * 64;

    // ---- load Q tile (hi/lo) and cache A-frags in registers ----
    {
        const __nv_bfloat16* gq  = Qh + base + (size_t)q0 * EMBED;
        const __nv_bfloat16* gql = Ql + base + (size_t)q0 * EMBED;
#pragma unroll
        for (int it = 0; it < 4; it++) {
            const int idx = tid + it * 128;
            const int r = idx >> 3, c = (idx & 7) << 3;
            *(uint4*)(sQh + r * FSTR + c) = *(const uint4*)(gq  + (size_t)r * EMBED + c);
            *(uint4*)(sQl + r * FSTR + c) = *(const uint4*)(gql + (size_t)r * EMBED + c);
        }
    }
    __syncthreads();

    uint32_t qfh[4][4], qfl[4][4];
    {
        const uint32_t aOff = ((wid * 16 + (lane & 15)) * FSTR + ((lane >> 4) << 3)) * 2;
        const uint32_t ah = smem_u32(sQh) + aOff;
        const uint32_t al = smem_u32(sQl) + aOff;
#pragma unroll
        for (int kf = 0; kf < 4; kf++) {
            ldsm_x4(ah + kf * 32, qfh[kf][0], qfh[kf][1], qfh[kf][2], qfh[kf][3]);
            ldsm_x4(al + kf * 32, qfl[kf][0], qfl[kf][1], qfl[kf][2], qfl[kf][3]);
        }
    }

    // B-frag lane addressing (shared by K and V loads)
    const uint32_t bg = lane >> 3;
    const uint32_t kOff = ((((bg >> 1) << 3) + (lane & 7)) * FSTR + ((bg & 1) << 3)) * 2;
    const uint32_t vOff = ((((bg & 1) << 3) + (lane & 7)) * FSTR + ((bg >> 1) << 3)) * 2;

    float ofr[8][4];
#pragma unroll
    for (int nf = 0; nf < 8; nf++)
#pragma unroll
        for (int q = 0; q < 4; q++) ofr[nf][q] = 0.0f;
    float m0 = -1e30f, m1 = -1e30f, l0 = 0.0f, l1 = 0.0f;

    const float SC = 0.18033688011112042f;   // 0.125 * log2(e)
    const int r0loc = wid * 16 + (lane >> 2);

    for (int j = 0; j <= qt; j++) {
        __syncthreads();
        {
            const size_t koff = base + (size_t)(j * 64) * EMBED;
            const __nv_bfloat16* gkh = Kh + koff;
            const __nv_bfloat16* gkl = Kl + koff;
            const __nv_bfloat16* gvh = Vh + koff;
            const __nv_bfloat16* gvl = Vl + koff;
#pragma unroll
            for (int it = 0; it < 4; it++) {
                const int idx = tid + it * 128;
                const int r = idx >> 3, c = (idx & 7) << 3;
                const size_t go = (size_t)r * EMBED + c;
                const int so = r * FSTR + c;
                *(uint4*)(sKh + so) = *(const uint4*)(gkh + go);
                *(uint4*)(sKl + so) = *(const uint4*)(gkl + go);
                *(uint4*)(sVh + so) = *(const uint4*)(gvh + go);
                *(uint4*)(sVl + so) = *(const uint4*)(gvl + go);
            }
        }
        __syncthreads();

        // ---- S = Q K^T (bf16x3) ----
        float sfr[8][4];
#pragma unroll
        for (int nf = 0; nf < 8; nf++)
#pragma unroll
            for (int q = 0; q < 4; q++) sfr[nf][q] = 0.0f;

        const uint32_t kh0 = smem_u32(sKh) + kOff;
        const uint32_t kl0 = smem_u32(sKl) + kOff;
#pragma unroll
        for (int ks = 0; ks < 4; ks++) {
            uint32_t bh[16], bl[16];
#pragma unroll
            for (int nb = 0; nb < 4; nb++) {
                const uint32_t d = nb * (16 * FSTR * 2) + ks * 32;
                ldsm_x4(kh0 + d, bh[nb*4+0], bh[nb*4+1], bh[nb*4+2], bh[nb*4+3]);
                ldsm_x4(kl0 + d, bl[nb*4+0], bl[nb*4+1], bl[nb*4+2], bl[nb*4+3]);
            }
#pragma unroll
            for (int nf = 0; nf < 8; nf++) {
                mma16816(sfr[nf], qfh[ks], &bh[nf*2]);
                mma16816(sfr[nf], qfh[ks], &bl[nf*2]);
                mma16816(sfr[nf], qfl[ks], &bh[nf*2]);
            }
        }

        // ---- scale + causal mask ----
        if (j == qt) {
#pragma unroll
            for (int nf = 0; nf < 8; nf++)
#pragma unroll
                for (int q = 0; q < 4; q++) {
                    const int col = nf * 8 + ((lane & 3) << 1) + (q & 1);
                    const int row = r0loc + ((q >> 1) << 3);
                    sfr[nf][q] = (col <= row) ? sfr[nf][q] * SC : -1e30f;
                }
        } else {
#pragma unroll
            for (int nf = 0; nf < 8; nf++)
#pragma unroll
                for (int q = 0; q < 4; q++) sfr[nf][q] *= SC;
        }

        // ---- online softmax (base-2, FFMA-pipe exp) ----
        float mx0 = -1e30f, mx1 = -1e30f;
#pragma unroll
        for (int nf = 0; nf < 8; nf++) {
            mx0 = fmaxf(mx0, fmaxf(sfr[nf][0], sfr[nf][1]));
            mx1 = fmaxf(mx1, fmaxf(sfr[nf][2], sfr[nf][3]));
        }
        mx0 = fmaxf(mx0, __shfl_xor_sync(0xffffffffu, mx0, 1));
        mx0 = fmaxf(mx0, __shfl_xor_sync(0xffffffffu, mx0, 2));
        mx1 = fmaxf(mx1, __shfl_xor_sync(0xffffffffu, mx1, 1));
        mx1 = fmaxf(mx1, __shfl_xor_sync(0xffffffffu, mx1, 2));

        const float mn0 = fmaxf(m0, mx0);
        const float mn1 = fmaxf(m1, mx1);
        const float a0 = fexp2(m0 - mn0);
        const float a1 = fexp2(m1 - mn1);
        m0 = mn0; m1 = mn1;

        float rs0 = 0.0f, rs1 = 0.0f;
#pragma unroll
        for (int nf = 0; nf < 8; nf++) {
            sfr[nf][0] = fexp2(sfr[nf][0] - mn0);
            sfr[nf][1] = fexp2(sfr[nf][1] - mn0);
            sfr[nf][2] = fexp2(sfr[nf][2] - mn1);
            sfr[nf][3] = fexp2(sfr[nf][3] - mn1);
            rs0 += sfr[nf][0] + sfr[nf][1];
            rs1 += sfr[nf][2] + sfr[nf][3];
        }
        rs0 += __shfl_xor_sync(0xffffffffu, rs0, 1);
        rs0 += __shfl_xor_sync(0xffffffffu, rs0, 2);
        rs1 += __shfl_xor_sync(0xffffffffu, rs1, 1);
        rs1 += __shfl_xor_sync(0xffffffffu, rs1, 2);
        l0 = l0 * a0 + rs0;
        l1 = l1 * a1 + rs1;

#pragma unroll
        for (int nf = 0; nf < 8; nf++) {
            ofr[nf][0] *= a0; ofr[nf][1] *= a0;
            ofr[nf][2] *= a1; ofr[nf][3] *= a1;
        }

        // ---- pack P into A-frags (C-frag -> A-frag layout identity) ----
        uint32_t pah[4][4], pal[4][4];
#pragma unroll
        for (int kf = 0; kf < 4; kf++) {
            split2(sfr[2*kf][0],   sfr[2*kf][1],   pah[kf][0], pal[kf][0]);
            split2(sfr[2*kf][2],   sfr[2*kf][3],   pah[kf][1], pal[kf][1]);
            split2(sfr[2*kf+1][0], sfr[2*kf+1][1], pah[kf][2], pal[kf][2]);
            split2(sfr[2*kf+1][2], sfr[2*kf+1][3], pah[kf][3], pal[kf][3]);
        }

        // ---- O += P V (bf16x3, V via ldmatrix.trans) ----
        const uint32_t vh0 = smem_u32(sVh) + vOff;
        const uint32_t vl0 = smem_u32(sVl) + vOff;
#pragma unroll
        for (int kf = 0; kf < 4; kf++) {
            uint32_t vh[16], vl[16];
#pragma unroll
            for (int nb = 0; nb < 4; nb++) {
                const uint32_t d = kf * (16 * FSTR * 2) + nb * 32;
                ldsm_x4_t(vh0 + d, vh[nb*4+0], vh[nb*4+1], vh[nb*4+2], vh[nb*4+3]);
                ldsm_x4_t(vl0 + d, vl[nb*4+0], vl[nb*4+1], vl[nb*4+2], vl[nb*4+3]);
            }
#pragma unroll
            for (int nf = 0; nf < 8; nf++) {
                mma16816(ofr[nf], pah[kf], &vh[nf*2]);
                mma16816(ofr[nf], pal[kf], &vh[nf*2]);
                mma16816(ofr[nf], pah[kf], &vl[nf*2]);
            }
        }
    }

    // ---- finalize: O /= l, write bf16 hi/lo split ----
    const float i0 = 1.0f / l0;
    const float i1 = 1.0f / l1;
    const int row0 = q0 + r0loc;
#pragma unroll
    for (int nf = 0; nf < 8; nf++) {
        const int col = nf * 8 + ((lane & 3) << 1);
        uint32_t h01, l01, h23, l23;
        split2(ofr[nf][0] * i0, ofr[nf][1] * i0, h01, l01);
        split2(ofr[nf][2] * i1, ofr[nf][3] * i1, h23, l23);
        const size_t o0 = base + (size_t)row0 * EMBED + col;
        const size_t o1 = base + (size_t)(row0 + 8) * EMBED + col;
        *(uint32_t*)(Oh + o0) = h01;
        *(uint32_t*)(Ol + o0) = l01;
        *(uint32_t*)(Oh + o1) = h23;
        *(uint32_t*)(Ol + o1) = l23;
    }
}

// ---------------------------------------------------------------------------
// Launch
// ---------------------------------------------------------------------------
extern "C" void kernel_launch(void* const* d_in, const int* in_sizes, int n_in,
                              void* d_out, int out_size)
{
    (void)in_sizes; (void)n_in; (void)out_size;
    const float* x  = (const float*)d_in[0];
    const float* Wq = (const float*)d_in[1];
    const float* bq = (const float*)d_in[2];
    const float* Wk = (const float*)d_in[3];
    const float* bk = (const float*)d_in[4];
    const float* Wv = (const float*)d_in[5];
    const float* bv = (const float*)d_in[6];
    const float* Wo = (const float*)d_in[7];
    const float* bo = (const float*)d_in[8];
    float* out = (float*)d_out;

    void *p;
    cudaGetSymbolAddress(&p, g_xhi); __nv_bfloat16* xhi = (__nv_bfloat16*)p;
    cudaGetSymbolAddress(&p, g_xlo); __nv_bfloat16* xlo = (__nv_bfloat16*)p;
    cudaGetSymbolAddress(&p, g_Qh);  __nv_bfloat16* Qh  = (__nv_bfloat16*)p;
    cudaGetSymbolAddress(&p, g_Ql);  __nv_bfloat16* Ql  = (__nv_bfloat16*)p;
    cudaGetSymbolAddress(&p, g_Kh);  __nv_bfloat16* Kh  = (__nv_bfloat16*)p;
    cudaGetSymbolAddress(&p, g_Kl);  __nv_bfloat16* Kl  = (__nv_bfloat16*)p;
    cudaGetSymbolAddress(&p, g_Vh);  __nv_bfloat16* Vh  = (__nv_bfloat16*)p;
    cudaGetSymbolAddress(&p, g_Vl);  __nv_bfloat16* Vl  = (__nv_bfloat16*)p;
    cudaGetSymbolAddress(&p, g_ahi); __nv_bfloat16* ahi = (__nv_bfloat16*)p;
    cudaGetSymbolAddress(&p, g_alo); __nv_bfloat16* alo = (__nv_bfloat16*)p;
    cudaGetSymbolAddress(&p, g_whi); __nv_bfloat16* whi = (__nv_bfloat16*)p;
    cudaGetSymbolAddress(&p, g_wlo); __nv_bfloat16* wlo = (__nv_bfloat16*)p;

    const size_t WSZ = (size_t)EMBED * EMBED;
    const int FLASH_SMEM = 6 * 64 * FSTR * 2;   // 55296 B
    cudaFuncSetAttribute(flash_attn, cudaFuncAttributeMaxDynamicSharedMemorySize,
                         FLASH_SMEM);

    // 1) fp32 -> bf16 hi/lo conversions
    conv_x<<<(NTOK * EMBED) / (256 * 4), 256>>>(x, xhi, xlo);
    conv_wT<<<dim3(32, 32, 4), dim3(32, 8)>>>(Wq, Wk, Wv, Wo, whi, wlo);

    // 2) fused QKV projection -> bf16 hi/lo split outputs
    dim3 g1(EMBED / 128, NTOK / 128, 3);
    gemm_mma<1><<<g1, 256>>>(xhi, xlo,
                             whi, whi + WSZ, whi + 2 * WSZ,
                             wlo, wlo + WSZ, wlo + 2 * WSZ,
                             bq, bk, bv, nullptr,
                             Qh, Kh, Vh, Ql, Kl, Vl);

    // 3) tensor-core causal flash attention
    dim3 g2(TSEQ / 64, NH, 2);
    flash_attn<<<g2, 128, FLASH_SMEM>>>(Qh, Ql, Kh, Kl, Vh, Vl, ahi, alo);

    // 4) output projection -> fp32
    dim3 g3(EMBED / 128, NTOK / 128, 1);
    gemm_mma<0><<<g3, 256>>>(ahi, alo,
                             whi + 3 * WSZ, whi + 3 * WSZ, whi + 3 * WSZ,
                             wlo + 3 * WSZ, wlo + 3 * WSZ, wlo + 3 * WSZ,
                             bo, bo, bo, out,
                             nullptr, nullptr, nullptr, nullptr, nullptr, nullptr);
}

// round 10
// speedup vs baseline: 1.1274x; 1.1274x over previous
#include <cuda_runtime.h>
#include <cuda_bf16.h>
#include <math.h>
#include <stdint.h>

// Problem constants
#define NTOK  4096      // B*T
#define TSEQ  2048
#define EMBED 1024
#define NH    16
#define HDIM  64

// ---------------------------------------------------------------------------
// Scratch (device globals: allocation-free per harness rules)
// ---------------------------------------------------------------------------
__device__ __nv_bfloat16 g_xhi[(size_t)NTOK * EMBED];
__device__ __nv_bfloat16 g_xlo[(size_t)NTOK * EMBED];
__device__ __nv_bfloat16 g_Qh[(size_t)NTOK * EMBED];
__device__ __nv_bfloat16 g_Ql[(size_t)NTOK * EMBED];
__device__ __nv_bfloat16 g_Kh[(size_t)NTOK * EMBED];
__device__ __nv_bfloat16 g_Kl[(size_t)NTOK * EMBED];
__device__ __nv_bfloat16 g_Vh[(size_t)NTOK * EMBED];
__device__ __nv_bfloat16 g_Vl[(size_t)NTOK * EMBED];
__device__ __nv_bfloat16 g_ahi[(size_t)NTOK * EMBED];
__device__ __nv_bfloat16 g_alo[(size_t)NTOK * EMBED];
__device__ __nv_bfloat16 g_whi[(size_t)4 * EMBED * EMBED];  // Wq^T,Wk^T,Wv^T,Wo^T
__device__ __nv_bfloat16 g_wlo[(size_t)4 * EMBED * EMBED];

// ---------------------------------------------------------------------------
// PTX helpers (compute_103-safe: ldmatrix + mma.sync + cp.async)
// ---------------------------------------------------------------------------
__device__ __forceinline__ uint32_t smem_u32(const void* p) {
    uint32_t a;
    asm("{ .reg .u64 t; cvta.to.shared.u64 t, %1; cvt.u32.u64 %0, t; }"
        : "=r"(a) : "l"(p));
    return a;
}

__device__ __forceinline__ void cp16(uint32_t dst, const void* src) {
    asm volatile("cp.async.cg.shared.global [%0], [%1], 16;"
                 :: "r"(dst), "l"(src));
}
#define CP_COMMIT() asm volatile("cp.async.commit_group;" ::: "memory")
#define CP_WAIT1()  asm volatile("cp.async.wait_group 1;" ::: "memory")

__device__ __forceinline__ void ldsm_x4(uint32_t addr, uint32_t& r0, uint32_t& r1,
                                        uint32_t& r2, uint32_t& r3) {
    asm volatile("ldmatrix.sync.aligned.m8n8.x4.shared.b16 {%0,%1,%2,%3}, [%4];"
                 : "=r"(r0), "=r"(r1), "=r"(r2), "=r"(r3) : "r"(addr));
}

__device__ __forceinline__ void ldsm_x4_t(uint32_t addr, uint32_t& r0, uint32_t& r1,
                                          uint32_t& r2, uint32_t& r3) {
    asm volatile("ldmatrix.sync.aligned.m8n8.x4.trans.shared.b16 {%0,%1,%2,%3}, [%4];"
                 : "=r"(r0), "=r"(r1), "=r"(r2), "=r"(r3) : "r"(addr));
}

__device__ __forceinline__ void mma16816(float* d, const uint32_t* a,
                                         const uint32_t* b) {
    asm volatile(
        "mma.sync.aligned.m16n8k16.row.col.f32.bf16.bf16.f32 "
        "{%0,%1,%2,%3}, {%4,%5,%6,%7}, {%8,%9}, {%0,%1,%2,%3};"
        : "+f"(d[0]), "+f"(d[1]), "+f"(d[2]), "+f"(d[3])
        : "r"(a[0]), "r"(a[1]), "r"(a[2]), "r"(a[3]), "r"(b[0]), "r"(b[1]));
}

// fp32 -> (bf16 hi, bf16 lo) split
__device__ __forceinline__ void split_bf16(float v, __nv_bfloat16& h, __nv_bfloat16& l) {
    h = __float2bfloat16(v);
    l = __float2bfloat16(v - __bfloat162float(h));
}

__device__ __forceinline__ void split2(float a, float b, uint32_t& hi, uint32_t& lo) {
    __nv_bfloat16 ha = __float2bfloat16(a);
    __nv_bfloat16 hb = __float2bfloat16(b);
    __nv_bfloat162 hp = __halves2bfloat162(ha, hb);
    hi = *reinterpret_cast<uint32_t*>(&hp);
    __nv_bfloat162 lp = __floats2bfloat162_rn(a - __bfloat162float(ha),
                                              b - __bfloat162float(hb));
    lo = *reinterpret_cast<uint32_t*>(&lp);
}

// Software exp2 on the FMA pipe (no MUFU). rel err ~2e-6.
__device__ __forceinline__ float fexp2(float x) {
    x = fmaxf(x, -125.0f);
    float t = __fadd_rn(x, 12582912.0f);
    int   k = __float_as_int(t) - 0x4B400000;
    float f = __fsub_rn(x, __fsub_rn(t, 12582912.0f));
    float p = 1.3333558146e-3f;
    p = fmaf(p, f, 9.6181291077e-3f);
    p = fmaf(p, f, 5.5504108664e-2f);
    p = fmaf(p, f, 2.4022650696e-1f);
    p = fmaf(p, f, 6.9314718056e-1f);
    p = fmaf(p, f, 1.0f);
    return p * __int_as_float((k + 127) << 23);
}

// ---------------------------------------------------------------------------
// Kernel 1: x -> xhi/xlo
// ---------------------------------------------------------------------------
__global__ __launch_bounds__(256)
void conv_x(const float* __restrict__ x, __nv_bfloat16* __restrict__ xhi,
            __nv_bfloat16* __restrict__ xlo)
{
    size_t i = ((size_t)blockIdx.x * 256 + threadIdx.x) * 4;
    float4 v = *(const float4*)(x + i);
    uint32_t h0, l0, h1, l1;
    split2(v.x, v.y, h0, l0);
    split2(v.z, v.w, h1, l1);
    uint2 ph, pl;
    ph.x = h0; ph.y = h1; pl.x = l0; pl.y = l1;
    *(uint2*)(xhi + i) = ph;
    *(uint2*)(xlo + i) = pl;
}

// ---------------------------------------------------------------------------
// Kernel 2: W [K,N] fp32 -> W^T [N,K] bf16 hi/lo (z selects among 4 weights)
// ---------------------------------------------------------------------------
__global__ __launch_bounds__(256)
void conv_wT(const float* __restrict__ W0, const float* __restrict__ W1,
             const float* __restrict__ W2, const float* __restrict__ W3,
             __nv_bfloat16* __restrict__ whi, __nv_bfloat16* __restrict__ wlo)
{
    __shared__ float tile[32][33];
    const float* W = W0;
    if (blockIdx.z == 1) W = W1;
    else if (blockIdx.z == 2) W = W2;
    else if (blockIdx.z == 3) W = W3;

    const int x = blockIdx.x * 32 + threadIdx.x;
    const int y = blockIdx.y * 32 + threadIdx.y;
#pragma unroll
    for (int j = 0; j < 32; j += 8)
        tile[threadIdx.y + j][threadIdx.x] = W[(size_t)(y + j) * EMBED + x];
    __syncthreads();

    const int xo = blockIdx.y * 32 + threadIdx.x;
    const int yo = blockIdx.x * 32 + threadIdx.y;
    const size_t zo = (size_t)blockIdx.z * EMBED * EMBED;
#pragma unroll
    for (int j = 0; j < 32; j += 8) {
        float v = tile[threadIdx.x][threadIdx.y + j];
        __nv_bfloat16 h, l;
        split_bf16(v, h, l);
        whi[zo + (size_t)(yo + j) * EMBED + xo] = h;
        wlo[zo + (size_t)(yo + j) * EMBED + xo] = l;
    }
}

// ---------------------------------------------------------------------------
// Kernel 3: bf16x3 GEMM on mma.sync.m16n8k16 + cp.async 2-stage pipeline
// ---------------------------------------------------------------------------
#define TSTR  40                     // padded k-stride (bf16 elems)
#define GT    (128 * TSTR * 2)       // tile bytes (10240)
#define GSTG  (4 * GT)               // stage bytes (40960)

__device__ __forceinline__ void cpa_tile(uint32_t sbase,
                                         const __nv_bfloat16* __restrict__ g,
                                         int tid)
{
#pragma unroll
    for (int it = 0; it < 2; it++) {
        const int c   = tid + it * 256;
        const int r   = c >> 2;
        const int col = (c & 3) << 3;
        cp16(sbase + (uint32_t)(r * TSTR + col) * 2, g + (size_t)r * EMBED + col);
    }
}

template<int SPLIT>
__global__ __launch_bounds__(256, 1)
void gemm_mma(const __nv_bfloat16* __restrict__ Ahi, const __nv_bfloat16* __restrict__ Alo,
              const __nv_bfloat16* __restrict__ Bh0, const __nv_bfloat16* __restrict__ Bh1,
              const __nv_bfloat16* __restrict__ Bh2,
              const __nv_bfloat16* __restrict__ Bl0, const __nv_bfloat16* __restrict__ Bl1,
              const __nv_bfloat16* __restrict__ Bl2,
              const float* __restrict__ c0, const float* __restrict__ c1,
              const float* __restrict__ c2,
              float* __restrict__ F0,
              __nv_bfloat16* __restrict__ H0, __nv_bfloat16* __restrict__ H1,
              __nv_bfloat16* __restrict__ H2,
              __nv_bfloat16* __restrict__ L0, __nv_bfloat16* __restrict__ L1,
              __nv_bfloat16* __restrict__ L2)
{
    extern __shared__ __align__(16) __nv_bfloat16 gsm[];
    const uint32_t sb = smem_u32(gsm);

    const __nv_bfloat16* Bhi = Bh0;
    const __nv_bfloat16* Blo = Bl0;
    const float* bias = c0;
    __nv_bfloat16* Dh = H0;
    __nv_bfloat16* Dl = L0;
    if (blockIdx.z == 1)      { Bhi = Bh1; Blo = Bl1; bias = c1; Dh = H1; Dl = L1; }
    else if (blockIdx.z == 2) { Bhi = Bh2; Blo = Bl2; bias = c2; Dh = H2; Dl = L2; }

    const int tid    = threadIdx.x;
    const int lane   = tid & 31;
    const int wid    = tid >> 5;
    const int warp_m = wid >> 2;
    const int warp_n = wid & 3;
    const int bm     = blockIdx.y * 128;
    const int bn     = blockIdx.x * 128;

    // within-tile ldmatrix offsets
    const uint32_t aRow = warp_m * 64 + (lane & 15);
    const uint32_t aOff = aRow * (TSTR * 2) + ((lane >> 4) << 4);
    const uint32_t bg   = lane >> 3;
    const uint32_t bRow = warp_n * 32 + ((bg >> 1) << 3) + (lane & 7);
    const uint32_t bOff = bRow * (TSTR * 2) + ((bg & 1) << 4);

    float acc[4][4][4];
#pragma unroll
    for (int i = 0; i < 4; i++)
#pragma unroll
        for (int j = 0; j < 4; j++)
#pragma unroll
            for (int q = 0; q < 4; q++) acc[i][j][q] = 0.0f;

    const __nv_bfloat16* gAh = Ahi + (size_t)bm * EMBED;
    const __nv_bfloat16* gAl = Alo + (size_t)bm * EMBED;
    const __nv_bfloat16* gBh = Bhi + (size_t)bn * EMBED;
    const __nv_bfloat16* gBl = Blo + (size_t)bn * EMBED;

    // prefetch stage 0
    {
        cpa_tile(sb,          gAh, tid);
        cpa_tile(sb + GT,     gAl, tid);
        cpa_tile(sb + 2 * GT, gBh, tid);
        cpa_tile(sb + 3 * GT, gBl, tid);
    }
    CP_COMMIT();

    for (int kb = 0; kb < EMBED / 32; kb++) {
        if (kb + 1 < EMBED / 32) {
            const int kc = (kb + 1) * 32;
            const uint32_t stB = sb + ((kb + 1) & 1) * GSTG;
            cpa_tile(stB,          gAh + kc, tid);
            cpa_tile(stB + GT,     gAl + kc, tid);
            cpa_tile(stB + 2 * GT, gBh + kc, tid);
            cpa_tile(stB + 3 * GT, gBl + kc, tid);
        }
        CP_COMMIT();
        CP_WAIT1();
        __syncthreads();

        const uint32_t stB = sb + (kb & 1) * GSTG;
        const uint32_t aHb = stB + aOff;
        const uint32_t aLb = stB + GT + aOff;
        const uint32_t bHb = stB + 2 * GT + bOff;
        const uint32_t bLb = stB + 3 * GT + bOff;

#pragma unroll
        for (int ks = 0; ks < 2; ks++) {
            uint32_t ah[4][4], al[4][4], bh[4][2], bl[4][2];
#pragma unroll
            for (int mi = 0; mi < 4; mi++) {
                const uint32_t d = mi * (16 * TSTR * 2) + ks * 32;
                ldsm_x4(aHb + d, ah[mi][0], ah[mi][1], ah[mi][2], ah[mi][3]);
                ldsm_x4(aLb + d, al[mi][0], al[mi][1], al[mi][2], al[mi][3]);
            }
#pragma unroll
            for (int np = 0; np < 2; np++) {
                const uint32_t d = np * (16 * TSTR * 2) + ks * 32;
                ldsm_x4(bHb + d, bh[np*2][0], bh[np*2][1], bh[np*2+1][0], bh[np*2+1][1]);
                ldsm_x4(bLb + d, bl[np*2][0], bl[np*2][1], bl[np*2+1][0], bl[np*2+1][1]);
            }
#pragma unroll
            for (int mi = 0; mi < 4; mi++)
#pragma unroll
                for (int ni = 0; ni < 4; ni++) {
                    mma16816(acc[mi][ni], ah[mi], bh[ni]);
                    mma16816(acc[mi][ni], ah[mi], bl[ni]);
                    mma16816(acc[mi][ni], al[mi], bh[ni]);
                }
        }
        __syncthreads();
    }

#pragma unroll
    for (int ni = 0; ni < 4; ni++) {
        const int col = bn + warp_n * 32 + ni * 8 + ((lane & 3) << 1);
        const float2 bv = *(const float2*)(bias + col);
#pragma unroll
        for (int mi = 0; mi < 4; mi++) {
            const int row = bm + warp_m * 64 + mi * 16 + (lane >> 2);
            const float a0 = acc[mi][ni][0] + bv.x;
            const float a1 = acc[mi][ni][1] + bv.y;
            const float a2 = acc[mi][ni][2] + bv.x;
            const float a3 = acc[mi][ni][3] + bv.y;
            if (SPLIT) {
                uint32_t h01, l01, h23, l23;
                split2(a0, a1, h01, l01);
                split2(a2, a3, h23, l23);
                *(uint32_t*)(Dh + (size_t)row * EMBED + col)       = h01;
                *(uint32_t*)(Dl + (size_t)row * EMBED + col)       = l01;
                *(uint32_t*)(Dh + (size_t)(row + 8) * EMBED + col) = h23;
                *(uint32_t*)(Dl + (size_t)(row + 8) * EMBED + col) = l23;
            } else {
                float2 o0, o1;
                o0.x = a0; o0.y = a1; o1.x = a2; o1.y = a3;
                *(float2*)(F0 + (size_t)row * EMBED + col)       = o0;
                *(float2*)(F0 + (size_t)(row + 8) * EMBED + col) = o1;
            }
        }
    }
}

// ---------------------------------------------------------------------------
// Kernel 4: tensor-core flash attention (causal) + cp.async K/V double buffer.
// ---------------------------------------------------------------------------
#define FSTR 72                  // padded row stride (bf16)
#define FT   (64 * FSTR * 2)     // tile bytes (9216)
// smem: Qh | Ql | stage0{Kh,Kl,Vh,Vl} | stage1{Kh,Kl,Vh,Vl}  = 10*FT = 92160 B

__device__ __forceinline__ void cpa64(uint32_t sbase,
                                      const __nv_bfloat16* __restrict__ g,
                                      int tid)
{
#pragma unroll
    for (int it = 0; it < 4; it++) {
        const int idx = tid + it * 128;
        const int r = idx >> 3, c = (idx & 7) << 3;
        cp16(sbase + (uint32_t)(r * FSTR + c) * 2, g + (size_t)r * EMBED + c);
    }
}

__global__ __launch_bounds__(128, 2)
void flash_attn(const __nv_bfloat16* __restrict__ Qh, const __nv_bfloat16* __restrict__ Ql,
                const __nv_bfloat16* __restrict__ Kh, const __nv_bfloat16* __restrict__ Kl,
                const __nv_bfloat16* __restrict__ Vh, const __nv_bfloat16* __restrict__ Vl,
                __nv_bfloat16* __restrict__ Oh, __nv_bfloat16* __restrict__ Ol)
{
    extern __shared__ __align__(16) __nv_bfloat16 sm[];
    const uint32_t sb = smem_u32(sm);

    const int tid  = threadIdx.x;
    const int lane = tid & 31;
    const int wid  = tid >> 5;
    const int qt   = gridDim.x - 1 - blockIdx.x;   // heavy tiles first
    const int h    = blockIdx.y;
    const int b    = blockIdx.z;

    const size_t base = (size_t)b * TSEQ * EMBED + (size_t)h * HDIM;
    const int q0 = qt * 64;

    // ---- prefetch K/V tile j=0 into stage 0 ----
    {
        const size_t koff = base;
        const uint32_t stB = sb + 2 * FT;
        cpa64(stB,          Kh + koff, tid);
        cpa64(stB + FT,     Kl + koff, tid);
        cpa64(stB + 2 * FT, Vh + koff, tid);
        cpa64(stB + 3 * FT, Vl + koff, tid);
    }
    CP_COMMIT();

    // ---- load Q tile (hi/lo) and cache A-frags in registers ----
    {
        const __nv_bfloat16* gq  = Qh + base + (size_t)q0 * EMBED;
        const __nv_bfloat16* gql = Ql + base + (size_t)q0 * EMBED;
        __nv_bfloat16* sQh = sm;
        __nv_bfloat16* sQl = sm + 64 * FSTR;
#pragma unroll
        for (int it = 0; it < 4; it++) {
            const int idx = tid + it * 128;
            const int r = idx >> 3, c = (idx & 7) << 3;
            *(uint4*)(sQh + r * FSTR + c) = *(const uint4*)(gq  + (size_t)r * EMBED + c);
            *(uint4*)(sQl + r * FSTR + c) = *(const uint4*)(gql + (size_t)r * EMBED + c);
        }
    }
    __syncthreads();

    uint32_t qfh[4][4], qfl[4][4];
    {
        const uint32_t aOff = ((wid * 16 + (lane & 15)) * FSTR + ((lane >> 4) << 3)) * 2;
        const uint32_t ah = sb + aOff;
        const uint32_t al = sb + FT + aOff;
#pragma unroll
        for (int kf = 0; kf < 4; kf++) {
            ldsm_x4(ah + kf * 32, qfh[kf][0], qfh[kf][1], qfh[kf][2], qfh[kf][3]);
            ldsm_x4(al + kf * 32, qfl[kf][0], qfl[kf][1], qfl[kf][2], qfl[kf][3]);
        }
    }

    // B-frag lane addressing (K normal, V trans)
    const uint32_t bg = lane >> 3;
    const uint32_t kOff = ((((bg >> 1) << 3) + (lane & 7)) * FSTR + ((bg & 1) << 3)) * 2;
    const uint32_t vOff = ((((bg & 1) << 3) + (lane & 7)) * FSTR + ((bg >> 1) << 3)) * 2;

    float ofr[8][4];
#pragma unroll
    for (int nf = 0; nf < 8; nf++)
#pragma unroll
        for (int q = 0; q < 4; q++) ofr[nf][q] = 0.0f;
    float m0 = -1e30f, m1 = -1e30f, l0 = 0.0f, l1 = 0.0f;

    const float SC = 0.18033688011112042f;   // 0.125 * log2(e)
    const int r0loc = wid * 16 + (lane >> 2);

    for (int j = 0; j <= qt; j++) {
        // prefetch next K/V tile into the other stage
        if (j < qt) {
            const size_t koff = base + (size_t)((j + 1) * 64) * EMBED;
            const uint32_t stB = sb + 2 * FT + ((j + 1) & 1) * 4 * FT;
            cpa64(stB,          Kh + koff, tid);
            cpa64(stB + FT,     Kl + koff, tid);
            cpa64(stB + 2 * FT, Vh + koff, tid);
            cpa64(stB + 3 * FT, Vl + koff, tid);
        }
        CP_COMMIT();
        CP_WAIT1();
        __syncthreads();

        const uint32_t stB = sb + 2 * FT + (j & 1) * 4 * FT;

        // ---- S = Q K^T (bf16x3) ----
        float sfr[8][4];
#pragma unroll
        for (int nf = 0; nf < 8; nf++)
#pragma unroll
            for (int q = 0; q < 4; q++) sfr[nf][q] = 0.0f;

        const uint32_t kh0 = stB + kOff;
        const uint32_t kl0 = stB + FT + kOff;
#pragma unroll
        for (int ks = 0; ks < 4; ks++) {
            uint32_t bh[16], bl[16];
#pragma unroll
            for (int nb = 0; nb < 4; nb++) {
                const uint32_t d = nb * (16 * FSTR * 2) + ks * 32;
                ldsm_x4(kh0 + d, bh[nb*4+0], bh[nb*4+1], bh[nb*4+2], bh[nb*4+3]);
                ldsm_x4(kl0 + d, bl[nb*4+0], bl[nb*4+1], bl[nb*4+2], bl[nb*4+3]);
            }
#pragma unroll
            for (int nf = 0; nf < 8; nf++) {
                mma16816(sfr[nf], qfh[ks], &bh[nf*2]);
                mma16816(sfr[nf], qfh[ks], &bl[nf*2]);
                mma16816(sfr[nf], qfl[ks], &bh[nf*2]);
            }
        }

        // ---- scale + causal mask ----
        if (j == qt) {
#pragma unroll
            for (int nf = 0; nf < 8; nf++)
#pragma unroll
                for (int q = 0; q < 4; q++) {
                    const int col = nf * 8 + ((lane & 3) << 1) + (q & 1);
                    const int row = r0loc + ((q >> 1) << 3);
                    sfr[nf][q] = (col <= row) ? sfr[nf][q] * SC : -1e30f;
                }
        } else {
#pragma unroll
            for (int nf = 0; nf < 8; nf++)
#pragma unroll
                for (int q = 0; q < 4; q++) sfr[nf][q] *= SC;
        }

        // ---- online softmax (base-2, FFMA-pipe exp) ----
        float mx0 = -1e30f, mx1 = -1e30f;
#pragma unroll
        for (int nf = 0; nf < 8; nf++) {
            mx0 = fmaxf(mx0, fmaxf(sfr[nf][0], sfr[nf][1]));
            mx1 = fmaxf(mx1, fmaxf(sfr[nf][2], sfr[nf][3]));
        }
        mx0 = fmaxf(mx0, __shfl_xor_sync(0xffffffffu, mx0, 1));
        mx0 = fmaxf(mx0, __shfl_xor_sync(0xffffffffu, mx0, 2));
        mx1 = fmaxf(mx1, __shfl_xor_sync(0xffffffffu, mx1, 1));
        mx1 = fmaxf(mx1, __shfl_xor_sync(0xffffffffu, mx1, 2));

        const float mn0 = fmaxf(m0, mx0);
        const float mn1 = fmaxf(m1, mx1);
        const float a0 = fexp2(m0 - mn0);
        const float a1 = fexp2(m1 - mn1);
        m0 = mn0; m1 = mn1;

        float rs0 = 0.0f, rs1 = 0.0f;
#pragma unroll
        for (int nf = 0; nf < 8; nf++) {
            sfr[nf][0] = fexp2(sfr[nf][0] - mn0);
            sfr[nf][1] = fexp2(sfr[nf][1] - mn0);
            sfr[nf][2] = fexp2(sfr[nf][2] - mn1);
            sfr[nf][3] = fexp2(sfr[nf][3] - mn1);
            rs0 += sfr[nf][0] + sfr[nf][1];
            rs1 += sfr[nf][2] + sfr[nf][3];
        }
        rs0 += __shfl_xor_sync(0xffffffffu, rs0, 1);
        rs0 += __shfl_xor_sync(0xffffffffu, rs0, 2);
        rs1 += __shfl_xor_sync(0xffffffffu, rs1, 1);
        rs1 += __shfl_xor_sync(0xffffffffu, rs1, 2);
        l0 = l0 * a0 + rs0;
        l1 = l1 * a1 + rs1;

#pragma unroll
        for (int nf = 0; nf < 8; nf++) {
            ofr[nf][0] *= a0; ofr[nf][1] *= a0;
            ofr[nf][2] *= a1; ofr[nf][3] *= a1;
        }

        // ---- pack P into A-frags ----
        uint32_t pah[4][4], pal[4][4];
#pragma unroll
        for (int kf = 0; kf < 4; kf++) {
            split2(sfr[2*kf][0],   sfr[2*kf][1],   pah[kf][0], pal[kf][0]);
            split2(sfr[2*kf][2],   sfr[2*kf][3],   pah[kf][1], pal[kf][1]);
            split2(sfr[2*kf+1][0], sfr[2*kf+1][1], pah[kf][2], pal[kf][2]);
            split2(sfr[2*kf+1][2], sfr[2*kf+1][3], pah[kf][3], pal[kf][3]);
        }

        // ---- O += P V (bf16x3, V via ldmatrix.trans) ----
        const uint32_t vh0 = stB + 2 * FT + vOff;
        const uint32_t vl0 = stB + 3 * FT + vOff;
#pragma unroll
        for (int kf = 0; kf < 4; kf++) {
            uint32_t vh[16], vl[16];
#pragma unroll
            for (int nb = 0; nb < 4; nb++) {
                const uint32_t d = kf * (16 * FSTR * 2) + nb * 32;
                ldsm_x4_t(vh0 + d, vh[nb*4+0], vh[nb*4+1], vh[nb*4+2], vh[nb*4+3]);
                ldsm_x4_t(vl0 + d, vl[nb*4+0], vl[nb*4+1], vl[nb*4+2], vl[nb*4+3]);
            }
#pragma unroll
            for (int nf = 0; nf < 8; nf++) {
                mma16816(ofr[nf], pah[kf], &vh[nf*2]);
                mma16816(ofr[nf], pal[kf], &vh[nf*2]);
                mma16816(ofr[nf], pah[kf], &vl[nf*2]);
            }
        }
        __syncthreads();
    }

    // ---- finalize: O /= l, write bf16 hi/lo split ----
    const float i0 = 1.0f / l0;
    const float i1 = 1.0f / l1;
    const int row0 = q0 + r0loc;
#pragma unroll
    for (int nf = 0; nf < 8; nf++) {
        const int col = nf * 8 + ((lane & 3) << 1);
        uint32_t h01, l01, h23, l23;
        split2(ofr[nf][0] * i0, ofr[nf][1] * i0, h01, l01);
        split2(ofr[nf][2] * i1, ofr[nf][3] * i1, h23, l23);
        const size_t o0 = base + (size_t)row0 * EMBED + col;
        const size_t o1 = base + (size_t)(row0 + 8) * EMBED + col;
        *(uint32_t*)(Oh + o0) = h01;
        *(uint32_t*)(Ol + o0) = l01;
        *(uint32_t*)(Oh + o1) = h23;
        *(uint32_t*)(Ol + o1) = l23;
    }
}

// ---------------------------------------------------------------------------
// Launch
// ---------------------------------------------------------------------------
extern "C" void kernel_launch(void* const* d_in, const int* in_sizes, int n_in,
                              void* d_out, int out_size)
{
    (void)in_sizes; (void)n_in; (void)out_size;
    const float* x  = (const float*)d_in[0];
    const float* Wq = (const float*)d_in[1];
    const float* bq = (const float*)d_in[2];
    const float* Wk = (const float*)d_in[3];
    const float* bk = (const float*)d_in[4];
    const float* Wv = (const float*)d_in[5];
    const float* bv = (const float*)d_in[6];
    const float* Wo = (const float*)d_in[7];
    const float* bo = (const float*)d_in[8];
    float* out = (float*)d_out;

    void *p;
    cudaGetSymbolAddress(&p, g_xhi); __nv_bfloat16* xhi = (__nv_bfloat16*)p;
    cudaGetSymbolAddress(&p, g_xlo); __nv_bfloat16* xlo = (__nv_bfloat16*)p;
    cudaGetSymbolAddress(&p, g_Qh);  __nv_bfloat16* Qh  = (__nv_bfloat16*)p;
    cudaGetSymbolAddress(&p, g_Ql);  __nv_bfloat16* Ql  = (__nv_bfloat16*)p;
    cudaGetSymbolAddress(&p, g_Kh);  __nv_bfloat16* Kh  = (__nv_bfloat16*)p;
    cudaGetSymbolAddress(&p, g_Kl);  __nv_bfloat16* Kl  = (__nv_bfloat16*)p;
    cudaGetSymbolAddress(&p, g_Vh);  __nv_bfloat16* Vh  = (__nv_bfloat16*)p;
    cudaGetSymbolAddress(&p, g_Vl);  __nv_bfloat16* Vl  = (__nv_bfloat16*)p;
    cudaGetSymbolAddress(&p, g_ahi); __nv_bfloat16* ahi = (__nv_bfloat16*)p;
    cudaGetSymbolAddress(&p, g_alo); __nv_bfloat16* alo = (__nv_bfloat16*)p;
    cudaGetSymbolAddress(&p, g_whi); __nv_bfloat16* whi = (__nv_bfloat16*)p;
    cudaGetSymbolAddress(&p, g_wlo); __nv_bfloat16* wlo = (__nv_bfloat16*)p;

    const size_t WSZ = (size_t)EMBED * EMBED;
    const int GEMM_SMEM  = 2 * GSTG;       // 81920 B
    const int FLASH_SMEM = 10 * FT;        // 92160 B
    cudaFuncSetAttribute(gemm_mma<1>, cudaFuncAttributeMaxDynamicSharedMemorySize,
                         GEMM_SMEM);
    cudaFuncSetAttribute(gemm_mma<0>, cudaFuncAttributeMaxDynamicSharedMemorySize,
                         GEMM_SMEM);
    cudaFuncSetAttribute(flash_attn, cudaFuncAttributeMaxDynamicSharedMemorySize,
                         FLASH_SMEM);

    // 1) fp32 -> bf16 hi/lo conversions
    conv_x<<<(NTOK * EMBED) / (256 * 4), 256>>>(x, xhi, xlo);
    conv_wT<<<dim3(32, 32, 4), dim3(32, 8)>>>(Wq, Wk, Wv, Wo, whi, wlo);

    // 2) fused QKV projection -> bf16 hi/lo split outputs
    dim3 g1(EMBED / 128, NTOK / 128, 3);
    gemm_mma<1><<<g1, 256, GEMM_SMEM>>>(xhi, xlo,
                                        whi, whi + WSZ, whi + 2 * WSZ,
                                        wlo, wlo + WSZ, wlo + 2 * WSZ,
                                        bq, bk, bv, nullptr,
                                        Qh, Kh, Vh, Ql, Kl, Vl);

    // 3) tensor-core causal flash attention (cp.async K/V pipeline)
    dim3 g2(TSEQ / 64, NH, 2);
    flash_attn<<<g2, 128, FLASH_SMEM>>>(Qh, Ql, Kh, Kl, Vh, Vl, ahi, alo);

    // 4) output projection -> fp32
    dim3 g3(EMBED / 128, NTOK / 128, 1);
    gemm_mma<0><<<g3, 256, GEMM_SMEM>>>(ahi, alo,
                                        whi + 3 * WSZ, whi + 3 * WSZ, whi + 3 * WSZ,
                                        wlo + 3 * WSZ, wlo + 3 * WSZ, wlo + 3 * WSZ,
                                        bo, bo, bo, out,
                                        nullptr, nullptr, nullptr, nullptr,
                                        nullptr, nullptr);
}

// round 11
// speedup vs baseline: 1.2246x; 1.0862x over previous
#include <cuda_runtime.h>
#include <cuda_bf16.h>
#include <math.h>
#include <stdint.h>

// Problem constants
#define NTOK  4096      // B*T
#define TSEQ  2048
#define EMBED 1024
#define NH    16
#define HDIM  64

// ---------------------------------------------------------------------------
// Scratch (device globals: allocation-free per harness rules)
// ---------------------------------------------------------------------------
__device__ __nv_bfloat16 g_xhi[(size_t)NTOK * EMBED];
__device__ __nv_bfloat16 g_xlo[(size_t)NTOK * EMBED];
__device__ __nv_bfloat16 g_Qh[(size_t)NTOK * EMBED];
__device__ __nv_bfloat16 g_Ql[(size_t)NTOK * EMBED];
__device__ __nv_bfloat16 g_Kh[(size_t)NTOK * EMBED];
__device__ __nv_bfloat16 g_Kl[(size_t)NTOK * EMBED];
__device__ __nv_bfloat16 g_Vh[(size_t)NTOK * EMBED];
__device__ __nv_bfloat16 g_Vl[(size_t)NTOK * EMBED];
__device__ __nv_bfloat16 g_ahi[(size_t)NTOK * EMBED];
__device__ __nv_bfloat16 g_alo[(size_t)NTOK * EMBED];
__device__ __nv_bfloat16 g_whi[(size_t)4 * EMBED * EMBED];  // Wq^T,Wk^T,Wv^T,Wo^T
__device__ __nv_bfloat16 g_wlo[(size_t)4 * EMBED * EMBED];

// ---------------------------------------------------------------------------
// PTX helpers (compute_103-safe: ldmatrix + mma.sync + cp.async)
// ---------------------------------------------------------------------------
__device__ __forceinline__ uint32_t smem_u32(const void* p) {
    uint32_t a;
    asm("{ .reg .u64 t; cvta.to.shared.u64 t, %1; cvt.u32.u64 %0, t; }"
        : "=r"(a) : "l"(p));
    return a;
}

__device__ __forceinline__ void cp16(uint32_t dst, const void* src) {
    asm volatile("cp.async.cg.shared.global [%0], [%1], 16;"
                 :: "r"(dst), "l"(src));
}
#define CP_COMMIT() asm volatile("cp.async.commit_group;" ::: "memory")
#define CP_WAIT0()  asm volatile("cp.async.wait_group 0;" ::: "memory")
#define CP_WAIT1()  asm volatile("cp.async.wait_group 1;" ::: "memory")

__device__ __forceinline__ void ldsm_x4(uint32_t addr, uint32_t& r0, uint32_t& r1,
                                        uint32_t& r2, uint32_t& r3) {
    asm volatile("ldmatrix.sync.aligned.m8n8.x4.shared.b16 {%0,%1,%2,%3}, [%4];"
                 : "=r"(r0), "=r"(r1), "=r"(r2), "=r"(r3) : "r"(addr));
}

__device__ __forceinline__ void ldsm_x4_t(uint32_t addr, uint32_t& r0, uint32_t& r1,
                                          uint32_t& r2, uint32_t& r3) {
    asm volatile("ldmatrix.sync.aligned.m8n8.x4.trans.shared.b16 {%0,%1,%2,%3}, [%4];"
                 : "=r"(r0), "=r"(r1), "=r"(r2), "=r"(r3) : "r"(addr));
}

__device__ __forceinline__ void mma16816(float* d, const uint32_t* a,
                                         const uint32_t* b) {
    asm volatile(
        "mma.sync.aligned.m16n8k16.row.col.f32.bf16.bf16.f32 "
        "{%0,%1,%2,%3}, {%4,%5,%6,%7}, {%8,%9}, {%0,%1,%2,%3};"
        : "+f"(d[0]), "+f"(d[1]), "+f"(d[2]), "+f"(d[3])
        : "r"(a[0]), "r"(a[1]), "r"(a[2]), "r"(a[3]), "r"(b[0]), "r"(b[1]));
}

// fp32 -> (bf16 hi, bf16 lo) split
__device__ __forceinline__ void split_bf16(float v, __nv_bfloat16& h, __nv_bfloat16& l) {
    h = __float2bfloat16(v);
    l = __float2bfloat16(v - __bfloat162float(h));
}

__device__ __forceinline__ void split2(float a, float b, uint32_t& hi, uint32_t& lo) {
    __nv_bfloat16 ha = __float2bfloat16(a);
    __nv_bfloat16 hb = __float2bfloat16(b);
    __nv_bfloat162 hp = __halves2bfloat162(ha, hb);
    hi = *reinterpret_cast<uint32_t*>(&hp);
    __nv_bfloat162 lp = __floats2bfloat162_rn(a - __bfloat162float(ha),
                                              b - __bfloat162float(hb));
    lo = *reinterpret_cast<uint32_t*>(&lp);
}

// Software exp2 on the FMA pipe (no MUFU). rel err ~2e-6.
__device__ __forceinline__ float fexp2(float x) {
    x = fmaxf(x, -125.0f);
    float t = __fadd_rn(x, 12582912.0f);
    int   k = __float_as_int(t) - 0x4B400000;
    float f = __fsub_rn(x, __fsub_rn(t, 12582912.0f));
    float p = 1.3333558146e-3f;
    p = fmaf(p, f, 9.6181291077e-3f);
    p = fmaf(p, f, 5.5504108664e-2f);
    p = fmaf(p, f, 2.4022650696e-1f);
    p = fmaf(p, f, 6.9314718056e-1f);
    p = fmaf(p, f, 1.0f);
    return p * __int_as_float((k + 127) << 23);
}

// ---------------------------------------------------------------------------
// Kernel 1: x -> xhi/xlo
// ---------------------------------------------------------------------------
__global__ __launch_bounds__(256)
void conv_x(const float* __restrict__ x, __nv_bfloat16* __restrict__ xhi,
            __nv_bfloat16* __restrict__ xlo)
{
    size_t i = ((size_t)blockIdx.x * 256 + threadIdx.x) * 4;
    float4 v = *(const float4*)(x + i);
    uint32_t h0, l0, h1, l1;
    split2(v.x, v.y, h0, l0);
    split2(v.z, v.w, h1, l1);
    uint2 ph, pl;
    ph.x = h0; ph.y = h1; pl.x = l0; pl.y = l1;
    *(uint2*)(xhi + i) = ph;
    *(uint2*)(xlo + i) = pl;
}

// ---------------------------------------------------------------------------
// Kernel 2: W [K,N] fp32 -> W^T [N,K] bf16 hi/lo (z selects among 4 weights)
// ---------------------------------------------------------------------------
__global__ __launch_bounds__(256)
void conv_wT(const float* __restrict__ W0, const float* __restrict__ W1,
             const float* __restrict__ W2, const float* __restrict__ W3,
             __nv_bfloat16* __restrict__ whi, __nv_bfloat16* __restrict__ wlo)
{
    __shared__ float tile[32][33];
    const float* W = W0;
    if (blockIdx.z == 1) W = W1;
    else if (blockIdx.z == 2) W = W2;
    else if (blockIdx.z == 3) W = W3;

    const int x = blockIdx.x * 32 + threadIdx.x;
    const int y = blockIdx.y * 32 + threadIdx.y;
#pragma unroll
    for (int j = 0; j < 32; j += 8)
        tile[threadIdx.y + j][threadIdx.x] = W[(size_t)(y + j) * EMBED + x];
    __syncthreads();

    const int xo = blockIdx.y * 32 + threadIdx.x;
    const int yo = blockIdx.x * 32 + threadIdx.y;
    const size_t zo = (size_t)blockIdx.z * EMBED * EMBED;
#pragma unroll
    for (int j = 0; j < 32; j += 8) {
        float v = tile[threadIdx.x][threadIdx.y + j];
        __nv_bfloat16 h, l;
        split_bf16(v, h, l);
        whi[zo + (size_t)(yo + j) * EMBED + xo] = h;
        wlo[zo + (size_t)(yo + j) * EMBED + xo] = l;
    }
}

// ---------------------------------------------------------------------------
// Kernel 3: bf16x3 GEMM on mma.sync.m16n8k16 + cp.async 2-stage pipeline
//   __launch_bounds__(256,2): regs capped 128 -> 2 CTAs/SM (smem 2x80KB fits)
// ---------------------------------------------------------------------------
#define TSTR  40                     // padded k-stride (bf16 elems)
#define GT    (128 * TSTR * 2)       // tile bytes (10240)
#define GSTG  (4 * GT)               // stage bytes (40960)

__device__ __forceinline__ void cpa_tile(uint32_t sbase,
                                         const __nv_bfloat16* __restrict__ g,
                                         int tid)
{
#pragma unroll
    for (int it = 0; it < 2; it++) {
        const int c   = tid + it * 256;
        const int r   = c >> 2;
        const int col = (c & 3) << 3;
        cp16(sbase + (uint32_t)(r * TSTR + col) * 2, g + (size_t)r * EMBED + col);
    }
}

template<int SPLIT>
__global__ __launch_bounds__(256, 2)
void gemm_mma(const __nv_bfloat16* __restrict__ Ahi, const __nv_bfloat16* __restrict__ Alo,
              const __nv_bfloat16* __restrict__ Bh0, const __nv_bfloat16* __restrict__ Bh1,
              const __nv_bfloat16* __restrict__ Bh2,
              const __nv_bfloat16* __restrict__ Bl0, const __nv_bfloat16* __restrict__ Bl1,
              const __nv_bfloat16* __restrict__ Bl2,
              const float* __restrict__ c0, const float* __restrict__ c1,
              const float* __restrict__ c2,
              float* __restrict__ F0,
              __nv_bfloat16* __restrict__ H0, __nv_bfloat16* __restrict__ H1,
              __nv_bfloat16* __restrict__ H2,
              __nv_bfloat16* __restrict__ L0, __nv_bfloat16* __restrict__ L1,
              __nv_bfloat16* __restrict__ L2)
{
    extern __shared__ __align__(16) __nv_bfloat16 gsm[];
    const uint32_t sb = smem_u32(gsm);

    const __nv_bfloat16* Bhi = Bh0;
    const __nv_bfloat16* Blo = Bl0;
    const float* bias = c0;
    __nv_bfloat16* Dh = H0;
    __nv_bfloat16* Dl = L0;
    if (blockIdx.z == 1)      { Bhi = Bh1; Blo = Bl1; bias = c1; Dh = H1; Dl = L1; }
    else if (blockIdx.z == 2) { Bhi = Bh2; Blo = Bl2; bias = c2; Dh = H2; Dl = L2; }

    const int tid    = threadIdx.x;
    const int lane   = tid & 31;
    const int wid    = tid >> 5;
    const int warp_m = wid >> 2;
    const int warp_n = wid & 3;
    const int bm     = blockIdx.y * 128;
    const int bn     = blockIdx.x * 128;

    const uint32_t aRow = warp_m * 64 + (lane & 15);
    const uint32_t aOff = aRow * (TSTR * 2) + ((lane >> 4) << 4);
    const uint32_t bg   = lane >> 3;
    const uint32_t bRow = warp_n * 32 + ((bg >> 1) << 3) + (lane & 7);
    const uint32_t bOff = bRow * (TSTR * 2) + ((bg & 1) << 4);

    float acc[4][4][4];
#pragma unroll
    for (int i = 0; i < 4; i++)
#pragma unroll
        for (int j = 0; j < 4; j++)
#pragma unroll
            for (int q = 0; q < 4; q++) acc[i][j][q] = 0.0f;

    const __nv_bfloat16* gAh = Ahi + (size_t)bm * EMBED;
    const __nv_bfloat16* gAl = Alo + (size_t)bm * EMBED;
    const __nv_bfloat16* gBh = Bhi + (size_t)bn * EMBED;
    const __nv_bfloat16* gBl = Blo + (size_t)bn * EMBED;

    // prefetch stage 0
    {
        cpa_tile(sb,          gAh, tid);
        cpa_tile(sb + GT,     gAl, tid);
        cpa_tile(sb + 2 * GT, gBh, tid);
        cpa_tile(sb + 3 * GT, gBl, tid);
    }
    CP_COMMIT();

    for (int kb = 0; kb < EMBED / 32; kb++) {
        if (kb + 1 < EMBED / 32) {
            const int kc = (kb + 1) * 32;
            const uint32_t stB = sb + ((kb + 1) & 1) * GSTG;
            cpa_tile(stB,          gAh + kc, tid);
            cpa_tile(stB + GT,     gAl + kc, tid);
            cpa_tile(stB + 2 * GT, gBh + kc, tid);
            cpa_tile(stB + 3 * GT, gBl + kc, tid);
        }
        CP_COMMIT();
        CP_WAIT1();
        __syncthreads();

        const uint32_t stB = sb + (kb & 1) * GSTG;
        const uint32_t aHb = stB + aOff;
        const uint32_t aLb = stB + GT + aOff;
        const uint32_t bHb = stB + 2 * GT + bOff;
        const uint32_t bLb = stB + 3 * GT + bOff;

#pragma unroll
        for (int ks = 0; ks < 2; ks++) {
            uint32_t ah[4][4], al[4][4], bh[4][2], bl[4][2];
#pragma unroll
            for (int mi = 0; mi < 4; mi++) {
                const uint32_t d = mi * (16 * TSTR * 2) + ks * 32;
                ldsm_x4(aHb + d, ah[mi][0], ah[mi][1], ah[mi][2], ah[mi][3]);
                ldsm_x4(aLb + d, al[mi][0], al[mi][1], al[mi][2], al[mi][3]);
            }
#pragma unroll
            for (int np = 0; np < 2; np++) {
                const uint32_t d = np * (16 * TSTR * 2) + ks * 32;
                ldsm_x4(bHb + d, bh[np*2][0], bh[np*2][1], bh[np*2+1][0], bh[np*2+1][1]);
                ldsm_x4(bLb + d, bl[np*2][0], bl[np*2][1], bl[np*2+1][0], bl[np*2+1][1]);
            }
            // term-outer ordering: consecutive MMAs hit independent accumulators
#pragma unroll
            for (int mi = 0; mi < 4; mi++)
#pragma unroll
                for (int ni = 0; ni < 4; ni++)
                    mma16816(acc[mi][ni], ah[mi], bh[ni]);
#pragma unroll
            for (int mi = 0; mi < 4; mi++)
#pragma unroll
                for (int ni = 0; ni < 4; ni++)
                    mma16816(acc[mi][ni], ah[mi], bl[ni]);
#pragma unroll
            for (int mi = 0; mi < 4; mi++)
#pragma unroll
                for (int ni = 0; ni < 4; ni++)
                    mma16816(acc[mi][ni], al[mi], bh[ni]);
        }
        __syncthreads();
    }

#pragma unroll
    for (int ni = 0; ni < 4; ni++) {
        const int col = bn + warp_n * 32 + ni * 8 + ((lane & 3) << 1);
        const float2 bv = *(const float2*)(bias + col);
#pragma unroll
        for (int mi = 0; mi < 4; mi++) {
            const int row = bm + warp_m * 64 + mi * 16 + (lane >> 2);
            const float a0 = acc[mi][ni][0] + bv.x;
            const float a1 = acc[mi][ni][1] + bv.y;
            const float a2 = acc[mi][ni][2] + bv.x;
            const float a3 = acc[mi][ni][3] + bv.y;
            if (SPLIT) {
                uint32_t h01, l01, h23, l23;
                split2(a0, a1, h01, l01);
                split2(a2, a3, h23, l23);
                *(uint32_t*)(Dh + (size_t)row * EMBED + col)       = h01;
                *(uint32_t*)(Dl + (size_t)row * EMBED + col)       = l01;
                *(uint32_t*)(Dh + (size_t)(row + 8) * EMBED + col) = h23;
                *(uint32_t*)(Dl + (size_t)(row + 8) * EMBED + col) = l23;
            } else {
                float2 o0, o1;
                o0.x = a0; o0.y = a1; o1.x = a2; o1.y = a3;
                *(float2*)(F0 + (size_t)row * EMBED + col)       = o0;
                *(float2*)(F0 + (size_t)(row + 8) * EMBED + col) = o1;
            }
        }
    }
}

// ---------------------------------------------------------------------------
// Kernel 4: tensor-core flash attention (causal).
//   K double-buffered (prefetch at iter top), V single-buffered with LATE
//   prefetch (issued after PV, overlaps next iter's QK+softmax).
//   smem = Qh,Ql,K0h,K0l,K1h,K1l,Vh,Vl = 8 tiles = 73728 B -> 3 CTAs/SM.
// ---------------------------------------------------------------------------
#define FSTR 72                  // padded row stride (bf16)
#define FT   (64 * FSTR * 2)     // tile bytes (9216)

__device__ __forceinline__ void cpa64(uint32_t sbase,
                                      const __nv_bfloat16* __restrict__ g,
                                      int tid)
{
#pragma unroll
    for (int it = 0; it < 4; it++) {
        const int idx = tid + it * 128;
        const int r = idx >> 3, c = (idx & 7) << 3;
        cp16(sbase + (uint32_t)(r * FSTR + c) * 2, g + (size_t)r * EMBED + c);
    }
}

__global__ __launch_bounds__(128, 3)
void flash_attn(const __nv_bfloat16* __restrict__ Qh, const __nv_bfloat16* __restrict__ Ql,
                const __nv_bfloat16* __restrict__ Kh, const __nv_bfloat16* __restrict__ Kl,
                const __nv_bfloat16* __restrict__ Vh, const __nv_bfloat16* __restrict__ Vl,
                __nv_bfloat16* __restrict__ Oh, __nv_bfloat16* __restrict__ Ol)
{
    extern __shared__ __align__(16) __nv_bfloat16 sm[];
    const uint32_t sb = smem_u32(sm);
    // layout: Qh | Ql | K0h | K0l | K1h | K1l | Vh | Vl

    const int tid  = threadIdx.x;
    const int lane = tid & 31;
    const int wid  = tid >> 5;
    const int qt   = gridDim.x - 1 - blockIdx.x;   // heavy tiles first
    const int h    = blockIdx.y;
    const int b    = blockIdx.z;

    const size_t base = (size_t)b * TSEQ * EMBED + (size_t)h * HDIM;
    const int q0 = qt * 64;

    // ---- prefetch K(0) [group], then V(0) [group] ----
    cpa64(sb + 2 * FT, Kh + base, tid);
    cpa64(sb + 3 * FT, Kl + base, tid);
    CP_COMMIT();
    cpa64(sb + 6 * FT, Vh + base, tid);
    cpa64(sb + 7 * FT, Vl + base, tid);
    CP_COMMIT();

    // ---- load Q tile (hi/lo), cache A-frags in registers ----
    {
        const __nv_bfloat16* gq  = Qh + base + (size_t)q0 * EMBED;
        const __nv_bfloat16* gql = Ql + base + (size_t)q0 * EMBED;
        __nv_bfloat16* sQh = sm;
        __nv_bfloat16* sQl = sm + 64 * FSTR;
#pragma unroll
        for (int it = 0; it < 4; it++) {
            const int idx = tid + it * 128;
            const int r = idx >> 3, c = (idx & 7) << 3;
            *(uint4*)(sQh + r * FSTR + c) = *(const uint4*)(gq  + (size_t)r * EMBED + c);
            *(uint4*)(sQl + r * FSTR + c) = *(const uint4*)(gql + (size_t)r * EMBED + c);
        }
    }
    __syncthreads();

    uint32_t qfh[4][4], qfl[4][4];
    {
        const uint32_t aOff = ((wid * 16 + (lane & 15)) * FSTR + ((lane >> 4) << 3)) * 2;
        const uint32_t ah = sb + aOff;
        const uint32_t al = sb + FT + aOff;
#pragma unroll
        for (int kf = 0; kf < 4; kf++) {
            ldsm_x4(ah + kf * 32, qfh[kf][0], qfh[kf][1], qfh[kf][2], qfh[kf][3]);
            ldsm_x4(al + kf * 32, qfl[kf][0], qfl[kf][1], qfl[kf][2], qfl[kf][3]);
        }
    }

    // B-frag lane addressing (K normal, V trans)
    const uint32_t bg = lane >> 3;
    const uint32_t kOff = ((((bg >> 1) << 3) + (lane & 7)) * FSTR + ((bg & 1) << 3)) * 2;
    const uint32_t vOff = ((((bg & 1) << 3) + (lane & 7)) * FSTR + ((bg >> 1) << 3)) * 2;

    float ofr[8][4];
#pragma unroll
    for (int nf = 0; nf < 8; nf++)
#pragma unroll
        for (int q = 0; q < 4; q++) ofr[nf][q] = 0.0f;
    float m0 = -1e30f, m1 = -1e30f, l0 = 0.0f, l1 = 0.0f;

    const float SC = 0.18033688011112042f;   // 0.125 * log2(e)
    const int r0loc = wid * 16 + (lane >> 2);

    for (int j = 0; j <= qt; j++) {
        // K(j) ready (V(j) may still be in flight as the newest group)
        CP_WAIT1();
        __syncthreads();

        // prefetch K(j+1) into the other K buffer
        if (j < qt) {
            const size_t koff = base + (size_t)((j + 1) * 64) * EMBED;
            const uint32_t kB = sb + (2 + 2 * ((j + 1) & 1)) * FT;
            cpa64(kB,      Kh + koff, tid);
            cpa64(kB + FT, Kl + koff, tid);
            CP_COMMIT();
        }

        const uint32_t kB = sb + (2 + 2 * (j & 1)) * FT;

        // ---- S = Q K^T (bf16x3) ----
        float sfr[8][4];
#pragma unroll
        for (int nf = 0; nf < 8; nf++)
#pragma unroll
            for (int q = 0; q < 4; q++) sfr[nf][q] = 0.0f;

        const uint32_t kh0 = kB + kOff;
        const uint32_t kl0 = kB + FT + kOff;
#pragma unroll
        for (int ks = 0; ks < 4; ks++) {
            uint32_t bh[16], bl[16];
#pragma unroll
            for (int nb = 0; nb < 4; nb++) {
                const uint32_t d = nb * (16 * FSTR * 2) + ks * 32;
                ldsm_x4(kh0 + d, bh[nb*4+0], bh[nb*4+1], bh[nb*4+2], bh[nb*4+3]);
                ldsm_x4(kl0 + d, bl[nb*4+0], bl[nb*4+1], bl[nb*4+2], bl[nb*4+3]);
            }
            // term-outer: independent accumulators back-to-back
#pragma unroll
            for (int nf = 0; nf < 8; nf++)
                mma16816(sfr[nf], qfh[ks], &bh[nf*2]);
#pragma unroll
            for (int nf = 0; nf < 8; nf++)
                mma16816(sfr[nf], qfh[ks], &bl[nf*2]);
#pragma unroll
            for (int nf = 0; nf < 8; nf++)
                mma16816(sfr[nf], qfl[ks], &bh[nf*2]);
        }

        // ---- scale + causal mask ----
        if (j == qt) {
#pragma unroll
            for (int nf = 0; nf < 8; nf++)
#pragma unroll
                for (int q = 0; q < 4; q++) {
                    const int col = nf * 8 + ((lane & 3) << 1) + (q & 1);
                    const int row = r0loc + ((q >> 1) << 3);
                    sfr[nf][q] = (col <= row) ? sfr[nf][q] * SC : -1e30f;
                }
        } else {
#pragma unroll
            for (int nf = 0; nf < 8; nf++)
#pragma unroll
                for (int q = 0; q < 4; q++) sfr[nf][q] *= SC;
        }

        // ---- online softmax (base-2, FFMA-pipe exp) ----
        float mx0 = -1e30f, mx1 = -1e30f;
#pragma unroll
        for (int nf = 0; nf < 8; nf++) {
            mx0 = fmaxf(mx0, fmaxf(sfr[nf][0], sfr[nf][1]));
            mx1 = fmaxf(mx1, fmaxf(sfr[nf][2], sfr[nf][3]));
        }
        mx0 = fmaxf(mx0, __shfl_xor_sync(0xffffffffu, mx0, 1));
        mx0 = fmaxf(mx0, __shfl_xor_sync(0xffffffffu, mx0, 2));
        mx1 = fmaxf(mx1, __shfl_xor_sync(0xffffffffu, mx1, 1));
        mx1 = fmaxf(mx1, __shfl_xor_sync(0xffffffffu, mx1, 2));

        const float mn0 = fmaxf(m0, mx0);
        const float mn1 = fmaxf(m1, mx1);
        const float a0 = fexp2(m0 - mn0);
        const float a1 = fexp2(m1 - mn1);
        m0 = mn0; m1 = mn1;

        float rs0 = 0.0f, rs1 = 0.0f;
#pragma unroll
        for (int nf = 0; nf < 8; nf++) {
            sfr[nf][0] = fexp2(sfr[nf][0] - mn0);
            sfr[nf][1] = fexp2(sfr[nf][1] - mn0);
            sfr[nf][2] = fexp2(sfr[nf][2] - mn1);
            sfr[nf][3] = fexp2(sfr[nf][3] - mn1);
            rs0 += sfr[nf][0] + sfr[nf][1];
            rs1 += sfr[nf][2] + sfr[nf][3];
        }
        rs0 += __shfl_xor_sync(0xffffffffu, rs0, 1);
        rs0 += __shfl_xor_sync(0xffffffffu, rs0, 2);
        rs1 += __shfl_xor_sync(0xffffffffu, rs1, 1);
        rs1 += __shfl_xor_sync(0xffffffffu, rs1, 2);
        l0 = l0 * a0 + rs0;
        l1 = l1 * a1 + rs1;

#pragma unroll
        for (int nf = 0; nf < 8; nf++) {
            ofr[nf][0] *= a0; ofr[nf][1] *= a0;
            ofr[nf][2] *= a1; ofr[nf][3] *= a1;
        }

        // ---- pack P into A-frags ----
        uint32_t pah[4][4], pal[4][4];
#pragma unroll
        for (int kf = 0; kf < 4; kf++) {
            split2(sfr[2*kf][0],   sfr[2*kf][1],   pah[kf][0], pal[kf][0]);
            split2(sfr[2*kf][2],   sfr[2*kf][3],   pah[kf][1], pal[kf][1]);
            split2(sfr[2*kf+1][0], sfr[2*kf+1][1], pah[kf][2], pal[kf][2]);
            split2(sfr[2*kf+1][2], sfr[2*kf+1][3], pah[kf][3], pal[kf][3]);
        }

        // ---- V(j) ready: wait leaves K(j+1) (if any) outstanding ----
        if (j < qt) { CP_WAIT1(); } else { CP_WAIT0(); }
        __syncthreads();

        // ---- O += P V (bf16x3, V via ldmatrix.trans) ----
        const uint32_t vh0 = sb + 6 * FT + vOff;
        const uint32_t vl0 = sb + 7 * FT + vOff;
#pragma unroll
        for (int kf = 0; kf < 4; kf++) {
            uint32_t vh[16], vl[16];
#pragma unroll
            for (int nb = 0; nb < 4; nb++) {
                const uint32_t d = kf * (16 * FSTR * 2) + nb * 32;
                ldsm_x4_t(vh0 + d, vh[nb*4+0], vh[nb*4+1], vh[nb*4+2], vh[nb*4+3]);
                ldsm_x4_t(vl0 + d, vl[nb*4+0], vl[nb*4+1], vl[nb*4+2], vl[nb*4+3]);
            }
#pragma unroll
            for (int nf = 0; nf < 8; nf++)
                mma16816(ofr[nf], pah[kf], &vh[nf*2]);
#pragma unroll
            for (int nf = 0; nf < 8; nf++)
                mma16816(ofr[nf], pal[kf], &vh[nf*2]);
#pragma unroll
            for (int nf = 0; nf < 8; nf++)
                mma16816(ofr[nf], pah[kf], &vl[nf*2]);
        }

        // ---- late V(j+1) prefetch: overlaps next iter's QK + softmax ----
        __syncthreads();   // all warps done reading V(j)
        if (j < qt) {
            const size_t koff = base + (size_t)((j + 1) * 64) * EMBED;
            cpa64(sb + 6 * FT, Vh + koff, tid);
            cpa64(sb + 7 * FT, Vl + koff, tid);
            CP_COMMIT();
        }
    }

    // ---- finalize: O /= l, write bf16 hi/lo split ----
    const float i0 = 1.0f / l0;
    const float i1 = 1.0f / l1;
    const int row0 = q0 + r0loc;
#pragma unroll
    for (int nf = 0; nf < 8; nf++) {
        const int col = nf * 8 + ((lane & 3) << 1);
        uint32_t h01, l01, h23, l23;
        split2(ofr[nf][0] * i0, ofr[nf][1] * i0, h01, l01);
        split2(ofr[nf][2] * i1, ofr[nf][3] * i1, h23, l23);
        const size_t o0 = base + (size_t)row0 * EMBED + col;
        const size_t o1 = base + (size_t)(row0 + 8) * EMBED + col;
        *(uint32_t*)(Oh + o0) = h01;
        *(uint32_t*)(Ol + o0) = l01;
        *(uint32_t*)(Oh + o1) = h23;
        *(uint32_t*)(Ol + o1) = l23;
    }
}

// ---------------------------------------------------------------------------
// Launch
// ---------------------------------------------------------------------------
extern "C" void kernel_launch(void* const* d_in, const int* in_sizes, int n_in,
                              void* d_out, int out_size)
{
    (void)in_sizes; (void)n_in; (void)out_size;
    const float* x  = (const float*)d_in[0];
    const float* Wq = (const float*)d_in[1];
    const float* bq = (const float*)d_in[2];
    const float* Wk = (const float*)d_in[3];
    const float* bk = (const float*)d_in[4];
    const float* Wv = (const float*)d_in[5];
    const float* bv = (const float*)d_in[6];
    const float* Wo = (const float*)d_in[7];
    const float* bo = (const float*)d_in[8];
    float* out = (float*)d_out;

    void *p;
    cudaGetSymbolAddress(&p, g_xhi); __nv_bfloat16* xhi = (__nv_bfloat16*)p;
    cudaGetSymbolAddress(&p, g_xlo); __nv_bfloat16* xlo = (__nv_bfloat16*)p;
    cudaGetSymbolAddress(&p, g_Qh);  __nv_bfloat16* Qh  = (__nv_bfloat16*)p;
    cudaGetSymbolAddress(&p, g_Ql);  __nv_bfloat16* Ql  = (__nv_bfloat16*)p;
    cudaGetSymbolAddress(&p, g_Kh);  __nv_bfloat16* Kh  = (__nv_bfloat16*)p;
    cudaGetSymbolAddress(&p, g_Kl);  __nv_bfloat16* Kl  = (__nv_bfloat16*)p;
    cudaGetSymbolAddress(&p, g_Vh);  __nv_bfloat16* Vh  = (__nv_bfloat16*)p;
    cudaGetSymbolAddress(&p, g_Vl);  __nv_bfloat16* Vl  = (__nv_bfloat16*)p;
    cudaGetSymbolAddress(&p, g_ahi); __nv_bfloat16* ahi = (__nv_bfloat16*)p;
    cudaGetSymbolAddress(&p, g_alo); __nv_bfloat16* alo = (__nv_bfloat16*)p;
    cudaGetSymbolAddress(&p, g_whi); __nv_bfloat16* whi = (__nv_bfloat16*)p;
    cudaGetSymbolAddress(&p, g_wlo); __nv_bfloat16* wlo = (__nv_bfloat16*)p;

    const size_t WSZ = (size_t)EMBED * EMBED;
    const int GEMM_SMEM  = 2 * GSTG;       // 81920 B
    const int FLASH_SMEM = 8 * FT;         // 73728 B -> 3 CTAs/SM
    cudaFuncSetAttribute(gemm_mma<1>, cudaFuncAttributeMaxDynamicSharedMemorySize,
                         GEMM_SMEM);
    cudaFuncSetAttribute(gemm_mma<0>, cudaFuncAttributeMaxDynamicSharedMemorySize,
                         GEMM_SMEM);
    cudaFuncSetAttribute(flash_attn, cudaFuncAttributeMaxDynamicSharedMemorySize,
                         FLASH_SMEM);

    // 1) fp32 -> bf16 hi/lo conversions
    conv_x<<<(NTOK * EMBED) / (256 * 4), 256>>>(x, xhi, xlo);
    conv_wT<<<dim3(32, 32, 4), dim3(32, 8)>>>(Wq, Wk, Wv, Wo, whi, wlo);

    // 2) fused QKV projection -> bf16 hi/lo split outputs
    dim3 g1(EMBED / 128, NTOK / 128, 3);
    gemm_mma<1><<<g1, 256, GEMM_SMEM>>>(xhi, xlo,
                                        whi, whi + WSZ, whi + 2 * WSZ,
                                        wlo, wlo + WSZ, wlo + 2 * WSZ,
                                        bq, bk, bv, nullptr,
                                        Qh, Kh, Vh, Ql, Kl, Vl);

    // 3) tensor-core causal flash attention
    dim3 g2(TSEQ / 64, NH, 2);
    flash_attn<<<g2, 128, FLASH_SMEM>>>(Qh, Ql, Kh, Kl, Vh, Vl, ahi, alo);

    // 4) output projection -> fp32
    dim3 g3(EMBED / 128, NTOK / 128, 1);
    gemm_mma<0><<<g3, 256, GEMM_SMEM>>>(ahi, alo,
                                        whi + 3 * WSZ, whi + 3 * WSZ, whi + 3 * WSZ,
                                        wlo + 3 * WSZ, wlo + 3 * WSZ, wlo + 3 * WSZ,
                                        bo, bo, bo, out,
                                        nullptr, nullptr, nullptr, nullptr,
                                        nullptr, nullptr);
}

// round 13
// speedup vs baseline: 1.2392x; 1.0119x over previous
#include <cuda_runtime.h>
#include <cuda_bf16.h>
#include <math.h>
#include <stdint.h>

// Problem constants
#define NTOK  4096      // B*T
#define TSEQ  2048
#define EMBED 1024
#define NH    16
#define HDIM  64

// ---------------------------------------------------------------------------
// Scratch (device globals: allocation-free per harness rules)
// ---------------------------------------------------------------------------
__device__ __nv_bfloat16 g_xhi[(size_t)NTOK * EMBED];
__device__ __nv_bfloat16 g_xlo[(size_t)NTOK * EMBED];
__device__ __nv_bfloat16 g_Qh[(size_t)NTOK * EMBED];
__device__ __nv_bfloat16 g_Ql[(size_t)NTOK * EMBED];
__device__ __nv_bfloat16 g_Kh[(size_t)NTOK * EMBED];
__device__ __nv_bfloat16 g_Kl[(size_t)NTOK * EMBED];
__device__ __nv_bfloat16 g_Vh[(size_t)NTOK * EMBED];
__device__ __nv_bfloat16 g_Vl[(size_t)NTOK * EMBED];
__device__ __nv_bfloat16 g_ahi[(size_t)NTOK * EMBED];
__device__ __nv_bfloat16 g_alo[(size_t)NTOK * EMBED];
__device__ __nv_bfloat16 g_whi[(size_t)4 * EMBED * EMBED];  // Wq^T,Wk^T,Wv^T,Wo^T
__device__ __nv_bfloat16 g_wlo[(size_t)4 * EMBED * EMBED];

// ---------------------------------------------------------------------------
// PTX helpers (compute_103-safe: ldmatrix + mma.sync + cp.async)
// ---------------------------------------------------------------------------
__device__ __forceinline__ uint32_t smem_u32(const void* p) {
    uint32_t a;
    asm("{ .reg .u64 t; cvta.to.shared.u64 t, %1; cvt.u32.u64 %0, t; }"
        : "=r"(a) : "l"(p));
    return a;
}

__device__ __forceinline__ void cp16(uint32_t dst, const void* src) {
    asm volatile("cp.async.cg.shared.global [%0], [%1], 16;"
                 :: "r"(dst), "l"(src));
}
#define CP_COMMIT() asm volatile("cp.async.commit_group;" ::: "memory")
#define CP_WAIT0()  asm volatile("cp.async.wait_group 0;" ::: "memory")
#define CP_WAIT1()  asm volatile("cp.async.wait_group 1;" ::: "memory")

__device__ __forceinline__ void ldsm_x4(uint32_t addr, uint32_t& r0, uint32_t& r1,
                                        uint32_t& r2, uint32_t& r3) {
    asm volatile("ldmatrix.sync.aligned.m8n8.x4.shared.b16 {%0,%1,%2,%3}, [%4];"
                 : "=r"(r0), "=r"(r1), "=r"(r2), "=r"(r3) : "r"(addr));
}

__device__ __forceinline__ void ldsm_x4_t(uint32_t addr, uint32_t& r0, uint32_t& r1,
                                          uint32_t& r2, uint32_t& r3) {
    asm volatile("ldmatrix.sync.aligned.m8n8.x4.trans.shared.b16 {%0,%1,%2,%3}, [%4];"
                 : "=r"(r0), "=r"(r1), "=r"(r2), "=r"(r3) : "r"(addr));
}

__device__ __forceinline__ void mma16816(float* d, const uint32_t* a,
                                         const uint32_t* b) {
    asm volatile(
        "mma.sync.aligned.m16n8k16.row.col.f32.bf16.bf16.f32 "
        "{%0,%1,%2,%3}, {%4,%5,%6,%7}, {%8,%9}, {%0,%1,%2,%3};"
        : "+f"(d[0]), "+f"(d[1]), "+f"(d[2]), "+f"(d[3])
        : "r"(a[0]), "r"(a[1]), "r"(a[2]), "r"(a[3]), "r"(b[0]), "r"(b[1]));
}

// fp32 -> (bf16 hi, bf16 lo) split
__device__ __forceinline__ void split_bf16(float v, __nv_bfloat16& h, __nv_bfloat16& l) {
    h = __float2bfloat16(v);
    l = __float2bfloat16(v - __bfloat162float(h));
}

__device__ __forceinline__ void split2(float a, float b, uint32_t& hi, uint32_t& lo) {
    __nv_bfloat16 ha = __float2bfloat16(a);
    __nv_bfloat16 hb = __float2bfloat16(b);
    __nv_bfloat162 hp = __halves2bfloat162(ha, hb);
    hi = *reinterpret_cast<uint32_t*>(&hp);
    __nv_bfloat162 lp = __floats2bfloat162_rn(a - __bfloat162float(ha),
                                              b - __bfloat162float(hb));
    lo = *reinterpret_cast<uint32_t*>(&lp);
}

// Software exp2 on the FMA pipe (no MUFU). rel err ~2e-6.
__device__ __forceinline__ float fexp2(float x) {
    x = fmaxf(x, -125.0f);
    float t = __fadd_rn(x, 12582912.0f);
    int   k = __float_as_int(t) - 0x4B400000;
    float f = __fsub_rn(x, __fsub_rn(t, 12582912.0f));
    float p = 1.3333558146e-3f;
    p = fmaf(p, f, 9.6181291077e-3f);
    p = fmaf(p, f, 5.5504108664e-2f);
    p = fmaf(p, f, 2.4022650696e-1f);
    p = fmaf(p, f, 6.9314718056e-1f);
    p = fmaf(p, f, 1.0f);
    return p * __int_as_float((k + 127) << 23);
}

// ---------------------------------------------------------------------------
// Kernel 1 (merged conversions):
//   z = 0..3 : W [K,N] fp32 -> W^T [N,K] bf16 hi/lo  (Wq,Wk,Wv,Wo)
//   z = 4..7 : x slab (z-4)*1024 rows -> xhi/xlo bf16 (same layout)
// ---------------------------------------------------------------------------
__global__ __launch_bounds__(256)
void conv_all(const float* __restrict__ x,
              const float* __restrict__ W0, const float* __restrict__ W1,
              const float* __restrict__ W2, const float* __restrict__ W3,
              __nv_bfloat16* __restrict__ xhi, __nv_bfloat16* __restrict__ xlo,
              __nv_bfloat16* __restrict__ whi, __nv_bfloat16* __restrict__ wlo)
{
    __shared__ float tile[32][33];
    const int z = blockIdx.z;

    if (z >= 4) {
        // activation split, no transpose
        const int c  = blockIdx.x * 32 + threadIdx.x;
        const int r0 = (z - 4) * 1024 + blockIdx.y * 32 + threadIdx.y;
#pragma unroll
        for (int j = 0; j < 32; j += 8) {
            const size_t idx = (size_t)(r0 + j) * EMBED + c;
            float v = x[idx];
            __nv_bfloat16 h, l;
            split_bf16(v, h, l);
            xhi[idx] = h;
            xlo[idx] = l;
        }
        return;
    }

    const float* W = W0;
    if (z == 1) W = W1;
    else if (z == 2) W = W2;
    else if (z == 3) W = W3;

    const int xc = blockIdx.x * 32 + threadIdx.x;
    const int yc = blockIdx.y * 32 + threadIdx.y;
#pragma unroll
    for (int j = 0; j < 32; j += 8)
        tile[threadIdx.y + j][threadIdx.x] = W[(size_t)(yc + j) * EMBED + xc];
    __syncthreads();

    const int xo = blockIdx.y * 32 + threadIdx.x;
    const int yo = blockIdx.x * 32 + threadIdx.y;
    const size_t zo = (size_t)z * EMBED * EMBED;
#pragma unroll
    for (int j = 0; j < 32; j += 8) {
        float v = tile[threadIdx.x][threadIdx.y + j];
        __nv_bfloat16 h, l;
        split_bf16(v, h, l);
        whi[zo + (size_t)(yo + j) * EMBED + xo] = h;
        wlo[zo + (size_t)(yo + j) * EMBED + xo] = l;
    }
}

// ---------------------------------------------------------------------------
// Kernel 2: bf16x3 GEMM on mma.sync.m16n8k16 + cp.async 2-stage pipeline
//   (R11 configuration: __launch_bounds__(256,2), term-outer MMA order)
// ---------------------------------------------------------------------------
#define TSTR  40                     // padded k-stride (bf16 elems)
#define GT    (128 * TSTR * 2)       // tile bytes (10240)
#define GSTG  (4 * GT)               // stage bytes (40960)

__device__ __forceinline__ void cpa_tile(uint32_t sbase,
                                         const __nv_bfloat16* __restrict__ g,
                                         int tid)
{
#pragma unroll
    for (int it = 0; it < 2; it++) {
        const int c   = tid + it * 256;
        const int r   = c >> 2;
        const int col = (c & 3) << 3;
        cp16(sbase + (uint32_t)(r * TSTR + col) * 2, g + (size_t)r * EMBED + col);
    }
}

template<int SPLIT>
__global__ __launch_bounds__(256, 2)
void gemm_mma(const __nv_bfloat16* __restrict__ Ahi, const __nv_bfloat16* __restrict__ Alo,
              const __nv_bfloat16* __restrict__ Bh0, const __nv_bfloat16* __restrict__ Bh1,
              const __nv_bfloat16* __restrict__ Bh2,
              const __nv_bfloat16* __restrict__ Bl0, const __nv_bfloat16* __restrict__ Bl1,
              const __nv_bfloat16* __restrict__ Bl2,
              const float* __restrict__ c0, const float* __restrict__ c1,
              const float* __restrict__ c2,
              float* __restrict__ F0,
              __nv_bfloat16* __restrict__ H0, __nv_bfloat16* __restrict__ H1,
              __nv_bfloat16* __restrict__ H2,
              __nv_bfloat16* __restrict__ L0, __nv_bfloat16* __restrict__ L1,
              __nv_bfloat16* __restrict__ L2)
{
    extern __shared__ __align__(16) __nv_bfloat16 gsm[];
    const uint32_t sb = smem_u32(gsm);

    const __nv_bfloat16* Bhi = Bh0;
    const __nv_bfloat16* Blo = Bl0;
    const float* bias = c0;
    __nv_bfloat16* Dh = H0;
    __nv_bfloat16* Dl = L0;
    if (blockIdx.z == 1)      { Bhi = Bh1; Blo = Bl1; bias = c1; Dh = H1; Dl = L1; }
    else if (blockIdx.z == 2) { Bhi = Bh2; Blo = Bl2; bias = c2; Dh = H2; Dl = L2; }

    const int tid    = threadIdx.x;
    const int lane   = tid & 31;
    const int wid    = tid >> 5;
    const int warp_m = wid >> 2;
    const int warp_n = wid & 3;
    const int bm     = blockIdx.y * 128;
    const int bn     = blockIdx.x * 128;

    const uint32_t aRow = warp_m * 64 + (lane & 15);
    const uint32_t aOff = aRow * (TSTR * 2) + ((lane >> 4) << 4);
    const uint32_t bg   = lane >> 3;
    const uint32_t bRow = warp_n * 32 + ((bg >> 1) << 3) + (lane & 7);
    const uint32_t bOff = bRow * (TSTR * 2) + ((bg & 1) << 4);

    float acc[4][4][4];
#pragma unroll
    for (int i = 0; i < 4; i++)
#pragma unroll
        for (int j = 0; j < 4; j++)
#pragma unroll
            for (int q = 0; q < 4; q++) acc[i][j][q] = 0.0f;

    const __nv_bfloat16* gAh = Ahi + (size_t)bm * EMBED;
    const __nv_bfloat16* gAl = Alo + (size_t)bm * EMBED;
    const __nv_bfloat16* gBh = Bhi + (size_t)bn * EMBED;
    const __nv_bfloat16* gBl = Blo + (size_t)bn * EMBED;

    // prefetch stage 0
    {
        cpa_tile(sb,          gAh, tid);
        cpa_tile(sb + GT,     gAl, tid);
        cpa_tile(sb + 2 * GT, gBh, tid);
        cpa_tile(sb + 3 * GT, gBl, tid);
    }
    CP_COMMIT();

    for (int kb = 0; kb < EMBED / 32; kb++) {
        if (kb + 1 < EMBED / 32) {
            const int kc = (kb + 1) * 32;
            const uint32_t stB = sb + ((kb + 1) & 1) * GSTG;
            cpa_tile(stB,          gAh + kc, tid);
            cpa_tile(stB + GT,     gAl + kc, tid);
            cpa_tile(stB + 2 * GT, gBh + kc, tid);
            cpa_tile(stB + 3 * GT, gBl + kc, tid);
        }
        CP_COMMIT();
        CP_WAIT1();
        __syncthreads();

        const uint32_t stB = sb + (kb & 1) * GSTG;
        const uint32_t aHb = stB + aOff;
        const uint32_t aLb = stB + GT + aOff;
        const uint32_t bHb = stB + 2 * GT + bOff;
        const uint32_t bLb = stB + 3 * GT + bOff;

#pragma unroll
        for (int ks = 0; ks < 2; ks++) {
            uint32_t ah[4][4], al[4][4], bh[4][2], bl[4][2];
#pragma unroll
            for (int mi = 0; mi < 4; mi++) {
                const uint32_t d = mi * (16 * TSTR * 2) + ks * 32;
                ldsm_x4(aHb + d, ah[mi][0], ah[mi][1], ah[mi][2], ah[mi][3]);
                ldsm_x4(aLb + d, al[mi][0], al[mi][1], al[mi][2], al[mi][3]);
            }
#pragma unroll
            for (int np = 0; np < 2; np++) {
                const uint32_t d = np * (16 * TSTR * 2) + ks * 32;
                ldsm_x4(bHb + d, bh[np*2][0], bh[np*2][1], bh[np*2+1][0], bh[np*2+1][1]);
                ldsm_x4(bLb + d, bl[np*2][0], bl[np*2][1], bl[np*2+1][0], bl[np*2+1][1]);
            }
            // term-outer ordering: consecutive MMAs hit independent accumulators
#pragma unroll
            for (int mi = 0; mi < 4; mi++)
#pragma unroll
                for (int ni = 0; ni < 4; ni++)
                    mma16816(acc[mi][ni], ah[mi], bh[ni]);
#pragma unroll
            for (int mi = 0; mi < 4; mi++)
#pragma unroll
                for (int ni = 0; ni < 4; ni++)
                    mma16816(acc[mi][ni], ah[mi], bl[ni]);
#pragma unroll
            for (int mi = 0; mi < 4; mi++)
#pragma unroll
                for (int ni = 0; ni < 4; ni++)
                    mma16816(acc[mi][ni], al[mi], bh[ni]);
        }
        __syncthreads();
    }

#pragma unroll
    for (int ni = 0; ni < 4; ni++) {
        const int col = bn + warp_n * 32 + ni * 8 + ((lane & 3) << 1);
        const float2 bv = *(const float2*)(bias + col);
#pragma unroll
        for (int mi = 0; mi < 4; mi++) {
            const int row = bm + warp_m * 64 + mi * 16 + (lane >> 2);
            const float a0 = acc[mi][ni][0] + bv.x;
            const float a1 = acc[mi][ni][1] + bv.y;
            const float a2 = acc[mi][ni][2] + bv.x;
            const float a3 = acc[mi][ni][3] + bv.y;
            if (SPLIT) {
                uint32_t h01, l01, h23, l23;
                split2(a0, a1, h01, l01);
                split2(a2, a3, h23, l23);
                *(uint32_t*)(Dh + (size_t)row * EMBED + col)       = h01;
                *(uint32_t*)(Dl + (size_t)row * EMBED + col)       = l01;
                *(uint32_t*)(Dh + (size_t)(row + 8) * EMBED + col) = h23;
                *(uint32_t*)(Dl + (size_t)(row + 8) * EMBED + col) = l23;
            } else {
                float2 o0, o1;
                o0.x = a0; o0.y = a1; o1.x = a2; o1.y = a3;
                *(float2*)(F0 + (size_t)row * EMBED + col)       = o0;
                *(float2*)(F0 + (size_t)(row + 8) * EMBED + col) = o1;
            }
        }
    }
}

// ---------------------------------------------------------------------------
// Kernel 3: tensor-core flash attention (causal) — R10 config (best measured):
//   K/V hi/lo all double-buffered via cp.async, 2 CTAs/SM.
//   smem: Qh | Ql | stage0{Kh,Kl,Vh,Vl} | stage1{Kh,Kl,Vh,Vl} = 10*FT = 92160 B
// ---------------------------------------------------------------------------
#define FSTR 72                  // padded row stride (bf16)
#define FT   (64 * FSTR * 2)     // tile bytes (9216)

__device__ __forceinline__ void cpa64(uint32_t sbase,
                                      const __nv_bfloat16* __restrict__ g,
                                      int tid)
{
#pragma unroll
    for (int it = 0; it < 4; it++) {
        const int idx = tid + it * 128;
        const int r = idx >> 3, c = (idx & 7) << 3;
        cp16(sbase + (uint32_t)(r * FSTR + c) * 2, g + (size_t)r * EMBED + c);
    }
}

__global__ __launch_bounds__(128, 2)
void flash_attn(const __nv_bfloat16* __restrict__ Qh, const __nv_bfloat16* __restrict__ Ql,
                const __nv_bfloat16* __restrict__ Kh, const __nv_bfloat16* __restrict__ Kl,
                const __nv_bfloat16* __restrict__ Vh, const __nv_bfloat16* __restrict__ Vl,
                __nv_bfloat16* __restrict__ Oh, __nv_bfloat16* __restrict__ Ol)
{
    extern __shared__ __align__(16) __nv_bfloat16 sm[];
    const uint32_t sb = smem_u32(sm);

    const int tid  = threadIdx.x;
    const int lane = tid & 31;
    const int wid  = tid >> 5;
    const int qt   = gridDim.x - 1 - blockIdx.x;   // heavy tiles first
    const int h    = blockIdx.y;
    const int b    = blockIdx.z;

    const size_t base = (size_t)b * TSEQ * EMBED + (size_t)h * HDIM;
    const int q0 = qt * 64;

    // ---- prefetch K/V tile j=0 into stage 0 ----
    {
        const size_t koff = base;
        const uint32_t stB = sb + 2 * FT;
        cpa64(stB,          Kh + koff, tid);
        cpa64(stB + FT,     Kl + koff, tid);
        cpa64(stB + 2 * FT, Vh + koff, tid);
        cpa64(stB + 3 * FT, Vl + koff, tid);
    }
    CP_COMMIT();

    // ---- load Q tile (hi/lo) and cache A-frags in registers ----
    {
        const __nv_bfloat16* gq  = Qh + base + (size_t)q0 * EMBED;
        const __nv_bfloat16* gql = Ql + base + (size_t)q0 * EMBED;
        __nv_bfloat16* sQh = sm;
        __nv_bfloat16* sQl = sm + 64 * FSTR;
#pragma unroll
        for (int it = 0; it < 4; it++) {
            const int idx = tid + it * 128;
            const int r = idx >> 3, c = (idx & 7) << 3;
            *(uint4*)(sQh + r * FSTR + c) = *(const uint4*)(gq  + (size_t)r * EMBED + c);
            *(uint4*)(sQl + r * FSTR + c) = *(const uint4*)(gql + (size_t)r * EMBED + c);
        }
    }
    __syncthreads();

    uint32_t qfh[4][4], qfl[4][4];
    {
        const uint32_t aOff = ((wid * 16 + (lane & 15)) * FSTR + ((lane >> 4) << 3)) * 2;
        const uint32_t ah = sb + aOff;
        const uint32_t al = sb + FT + aOff;
#pragma unroll
        for (int kf = 0; kf < 4; kf++) {
            ldsm_x4(ah + kf * 32, qfh[kf][0], qfh[kf][1], qfh[kf][2], qfh[kf][3]);
            ldsm_x4(al + kf * 32, qfl[kf][0], qfl[kf][1], qfl[kf][2], qfl[kf][3]);
        }
    }

    // B-frag lane addressing (K normal, V trans)
    const uint32_t bg = lane >> 3;
    const uint32_t kOff = ((((bg >> 1) << 3) + (lane & 7)) * FSTR + ((bg & 1) << 3)) * 2;
    const uint32_t vOff = ((((bg & 1) << 3) + (lane & 7)) * FSTR + ((bg >> 1) << 3)) * 2;

    float ofr[8][4];
#pragma unroll
    for (int nf = 0; nf < 8; nf++)
#pragma unroll
        for (int q = 0; q < 4; q++) ofr[nf][q] = 0.0f;
    float m0 = -1e30f, m1 = -1e30f, l0 = 0.0f, l1 = 0.0f;

    const float SC = 0.18033688011112042f;   // 0.125 * log2(e)
    const int r0loc = wid * 16 + (lane >> 2);

    for (int j = 0; j <= qt; j++) {
        // prefetch next K/V tile into the other stage
        if (j < qt) {
            const size_t koff = base + (size_t)((j + 1) * 64) * EMBED;
            const uint32_t stB = sb + 2 * FT + ((j + 1) & 1) * 4 * FT;
            cpa64(stB,          Kh + koff, tid);
            cpa64(stB + FT,     Kl + koff, tid);
            cpa64(stB + 2 * FT, Vh + koff, tid);
            cpa64(stB + 3 * FT, Vl + koff, tid);
        }
        CP_COMMIT();
        CP_WAIT1();
        __syncthreads();

        const uint32_t stB = sb + 2 * FT + (j & 1) * 4 * FT;

        // ---- S = Q K^T (bf16x3) ----
        float sfr[8][4];
#pragma unroll
        for (int nf = 0; nf < 8; nf++)
#pragma unroll
            for (int q = 0; q < 4; q++) sfr[nf][q] = 0.0f;

        const uint32_t kh0 = stB + kOff;
        const uint32_t kl0 = stB + FT + kOff;
#pragma unroll
        for (int ks = 0; ks < 4; ks++) {
            uint32_t bh[16], bl[16];
#pragma unroll
            for (int nb = 0; nb < 4; nb++) {
                const uint32_t d = nb * (16 * FSTR * 2) + ks * 32;
                ldsm_x4(kh0 + d, bh[nb*4+0], bh[nb*4+1], bh[nb*4+2], bh[nb*4+3]);
                ldsm_x4(kl0 + d, bl[nb*4+0], bl[nb*4+1], bl[nb*4+2], bl[nb*4+3]);
            }
            // term-outer: independent accumulators back-to-back
#pragma unroll
            for (int nf = 0; nf < 8; nf++)
                mma16816(sfr[nf], qfh[ks], &bh[nf*2]);
#pragma unroll
            for (int nf = 0; nf < 8; nf++)
                mma16816(sfr[nf], qfh[ks], &bl[nf*2]);
#pragma unroll
            for (int nf = 0; nf < 8; nf++)
                mma16816(sfr[nf], qfl[ks], &bh[nf*2]);
        }

        // ---- scale + causal mask ----
        if (j == qt) {
#pragma unroll
            for (int nf = 0; nf < 8; nf++)
#pragma unroll
                for (int q = 0; q < 4; q++) {
                    const int col = nf * 8 + ((lane & 3) << 1) + (q & 1);
                    const int row = r0loc + ((q >> 1) << 3);
                    sfr[nf][q] = (col <= row) ? sfr[nf][q] * SC : -1e30f;
                }
        } else {
#pragma unroll
            for (int nf = 0; nf < 8; nf++)
#pragma unroll
                for (int q = 0; q < 4; q++) sfr[nf][q] *= SC;
        }

        // ---- online softmax (base-2, FFMA-pipe exp) ----
        float mx0 = -1e30f, mx1 = -1e30f;
#pragma unroll
        for (int nf = 0; nf < 8; nf++) {
            mx0 = fmaxf(mx0, fmaxf(sfr[nf][0], sfr[nf][1]));
            mx1 = fmaxf(mx1, fmaxf(sfr[nf][2], sfr[nf][3]));
        }
        mx0 = fmaxf(mx0, __shfl_xor_sync(0xffffffffu, mx0, 1));
        mx0 = fmaxf(mx0, __shfl_xor_sync(0xffffffffu, mx0, 2));
        mx1 = fmaxf(mx1, __shfl_xor_sync(0xffffffffu, mx1, 1));
        mx1 = fmaxf(mx1, __shfl_xor_sync(0xffffffffu, mx1, 2));

        const float mn0 = fmaxf(m0, mx0);
        const float mn1 = fmaxf(m1, mx1);
        const float a0 = fexp2(m0 - mn0);
        const float a1 = fexp2(m1 - mn1);
        m0 = mn0; m1 = mn1;

        float rs0 = 0.0f, rs1 = 0.0f;
#pragma unroll
        for (int nf = 0; nf < 8; nf++) {
            sfr[nf][0] = fexp2(sfr[nf][0] - mn0);
            sfr[nf][1] = fexp2(sfr[nf][1] - mn0);
            sfr[nf][2] = fexp2(sfr[nf][2] - mn1);
            sfr[nf][3] = fexp2(sfr[nf][3] - mn1);
            rs0 += sfr[nf][0] + sfr[nf][1];
            rs1 += sfr[nf][2] + sfr[nf][3];
        }
        rs0 += __shfl_xor_sync(0xffffffffu, rs0, 1);
        rs0 += __shfl_xor_sync(0xffffffffu, rs0, 2);
        rs1 += __shfl_xor_sync(0xffffffffu, rs1, 1);
        rs1 += __shfl_xor_sync(0xffffffffu, rs1, 2);
        l0 = l0 * a0 + rs0;
        l1 = l1 * a1 + rs1;

#pragma unroll
        for (int nf = 0; nf < 8; nf++) {
            ofr[nf][0] *= a0; ofr[nf][1] *= a0;
            ofr[nf][2] *= a1; ofr[nf][3] *= a1;
        }

        // ---- pack P into A-frags ----
        uint32_t pah[4][4], pal[4][4];
#pragma unroll
        for (int kf = 0; kf < 4; kf++) {
            split2(sfr[2*kf][0],   sfr[2*kf][1],   pah[kf][0], pal[kf][0]);
            split2(sfr[2*kf][2],   sfr[2*kf][3],   pah[kf][1], pal[kf][1]);
            split2(sfr[2*kf+1][0], sfr[2*kf+1][1], pah[kf][2], pal[kf][2]);
            split2(sfr[2*kf+1][2], sfr[2*kf+1][3], pah[kf][3], pal[kf][3]);
        }

        // ---- O += P V (bf16x3, V via ldmatrix.trans) ----
        const uint32_t vh0 = stB + 2 * FT + vOff;
        const uint32_t vl0 = stB + 3 * FT + vOff;
#pragma unroll
        for (int kf = 0; kf < 4; kf++) {
            uint32_t vh[16], vl[16];
#pragma unroll
            for (int nb = 0; nb < 4; nb++) {
                const uint32_t d = kf * (16 * FSTR * 2) + nb * 32;
                ldsm_x4_t(vh0 + d, vh[nb*4+0], vh[nb*4+1], vh[nb*4+2], vh[nb*4+3]);
                ldsm_x4_t(vl0 + d, vl[nb*4+0], vl[nb*4+1], vl[nb*4+2], vl[nb*4+3]);
            }
#pragma unroll
            for (int nf = 0; nf < 8; nf++)
                mma16816(ofr[nf], pah[kf], &vh[nf*2]);
#pragma unroll
            for (int nf = 0; nf < 8; nf++)
                mma16816(ofr[nf], pal[kf], &vh[nf*2]);
#pragma unroll
            for (int nf = 0; nf < 8; nf++)
                mma16816(ofr[nf], pah[kf], &vl[nf*2]);
        }
        __syncthreads();
    }

    // ---- finalize: O /= l, write bf16 hi/lo split ----
    const float i0 = 1.0f / l0;
    const float i1 = 1.0f / l1;
    const int row0 = q0 + r0loc;
#pragma unroll
    for (int nf = 0; nf < 8; nf++) {
        const int col = nf * 8 + ((lane & 3) << 1);
        uint32_t h01, l01, h23, l23;
        split2(ofr[nf][0] * i0, ofr[nf][1] * i0, h01, l01);
        split2(ofr[nf][2] * i1, ofr[nf][3] * i1, h23, l23);
        const size_t o0 = base + (size_t)row0 * EMBED + col;
        const size_t o1 = base + (size_t)(row0 + 8) * EMBED + col;
        *(uint32_t*)(Oh + o0) = h01;
        *(uint32_t*)(Ol + o0) = l01;
        *(uint32_t*)(Oh + o1) = h23;
        *(uint32_t*)(Ol + o1) = l23;
    }
}

// ---------------------------------------------------------------------------
// Launch
// ---------------------------------------------------------------------------
extern "C" void kernel_launch(void* const* d_in, const int* in_sizes, int n_in,
                              void* d_out, int out_size)
{
    (void)in_sizes; (void)n_in; (void)out_size;
    const float* x  = (const float*)d_in[0];
    const float* Wq = (const float*)d_in[1];
    const float* bq = (const float*)d_in[2];
    const float* Wk = (const float*)d_in[3];
    const float* bk = (const float*)d_in[4];
    const float* Wv = (const float*)d_in[5];
    const float* bv = (const float*)d_in[6];
    const float* Wo = (const float*)d_in[7];
    const float* bo = (const float*)d_in[8];
    float* out = (float*)d_out;

    void *p;
    cudaGetSymbolAddress(&p, g_xhi); __nv_bfloat16* xhi = (__nv_bfloat16*)p;
    cudaGetSymbolAddress(&p, g_xlo); __nv_bfloat16* xlo = (__nv_bfloat16*)p;
    cudaGetSymbolAddress(&p, g_Qh);  __nv_bfloat16* Qh  = (__nv_bfloat16*)p;
    cudaGetSymbolAddress(&p, g_Ql);  __nv_bfloat16* Ql  = (__nv_bfloat16*)p;
    cudaGetSymbolAddress(&p, g_Kh);  __nv_bfloat16* Kh  = (__nv_bfloat16*)p;
    cudaGetSymbolAddress(&p, g_Kl);  __nv_bfloat16* Kl  = (__nv_bfloat16*)p;
    cudaGetSymbolAddress(&p, g_Vh);  __nv_bfloat16* Vh  = (__nv_bfloat16*)p;
    cudaGetSymbolAddress(&p, g_Vl);  __nv_bfloat16* Vl  = (__nv_bfloat16*)p;
    cudaGetSymbolAddress(&p, g_ahi); __nv_bfloat16* ahi = (__nv_bfloat16*)p;
    cudaGetSymbolAddress(&p, g_alo); __nv_bfloat16* alo = (__nv_bfloat16*)p;
    cudaGetSymbolAddress(&p, g_whi); __nv_bfloat16* whi = (__nv_bfloat16*)p;
    cudaGetSymbolAddress(&p, g_wlo); __nv_bfloat16* wlo = (__nv_bfloat16*)p;

    const size_t WSZ = (size_t)EMBED * EMBED;
    const int GEMM_SMEM  = 2 * GSTG;       // 81920 B
    const int FLASH_SMEM = 10 * FT;        // 92160 B -> 2 CTAs/SM (best measured)
    cudaFuncSetAttribute(gemm_mma<1>, cudaFuncAttributeMaxDynamicSharedMemorySize,
                         GEMM_SMEM);
    cudaFuncSetAttribute(gemm_mma<0>, cudaFuncAttributeMaxDynamicSharedMemorySize,
                         GEMM_SMEM);
    cudaFuncSetAttribute(flash_attn, cudaFuncAttributeMaxDynamicSharedMemorySize,
                         FLASH_SMEM);

    // 1) fp32 -> bf16 hi/lo conversions (single merged launch)
    conv_all<<<dim3(32, 32, 8), dim3(32, 8)>>>(x, Wq, Wk, Wv, Wo,
                                               xhi, xlo, whi, wlo);

    // 2) fused QKV projection -> bf16 hi/lo split outputs
    dim3 g1(EMBED / 128, NTOK / 128, 3);
    gemm_mma<1><<<g1, 256, GEMM_SMEM>>>(xhi, xlo,
                                        whi, whi + WSZ, whi + 2 * WSZ,
                                        wlo, wlo + WSZ, wlo + 2 * WSZ,
                                        bq, bk, bv, nullptr,
                                        Qh, Kh, Vh, Ql, Kl, Vl);

    // 3) tensor-core causal flash attention (R10 double-buffered config)
    dim3 g2(TSEQ / 64, NH, 2);
    flash_attn<<<g2, 128, FLASH_SMEM>>>(Qh, Ql, Kh, Kl, Vh, Vl, ahi, alo);

    // 4) output projection -> fp32
    dim3 g3(EMBED / 128, NTOK / 128, 1);
    gemm_mma<0><<<g3, 256, GEMM_SMEM>>>(ahi, alo,
                                        whi + 3 * WSZ, whi + 3 * WSZ, whi + 3 * WSZ,
                                        wlo + 3 * WSZ, wlo + 3 * WSZ, wlo + 3 * WSZ,
                                        bo, bo, bo, out,
                                        nullptr, nullptr, nullptr, nullptr,
                                        nullptr, nullptr);
}